// round 8
// baseline (speedup 1.0000x reference)
#include <cuda_runtime.h>
#include <cuda_bf16.h>
#include <math.h>
#include <stdint.h>

// Problem constants
#define BQ   512
#define LQ   128
#define MQ   6
#define AD   39
#define BD   10
#define CD   49
#define FPD  256
#define NATOMS (BQ * LQ)   // 65536

// ---------------------------------------------------------------------------
// Device-global scratch (allocation-free rule)
// ---------------------------------------------------------------------------
__device__ __align__(16) float g_af[NATOMS * FPD];
__device__ __align__(16) float g_asum[NATOMS];
__device__ __align__(16) __nv_bfloat16 g_s_hi[NATOMS * FPD],  g_s_lo[NATOMS * FPD];
__device__ __align__(16) __nv_bfloat16 g_af_hi[NATOMS * FPD], g_af_lo[NATOMS * FPD];
__device__ __align__(16) __nv_bfloat16 g_cx_hi[NATOMS * FPD], g_cx_lo[NATOMS * FPD];
__device__ __align__(16) __nv_bfloat16 g_Wat_h[FPD * FPD],     g_Wat_l[FPD * FPD];
__device__ __align__(16) __nv_bfloat16 g_Wih_h[3 * FPD * FPD], g_Wih_l[3 * FPD * FPD];
__device__ __align__(16) __nv_bfloat16 g_Whh_h[3 * FPD * FPD], g_Whh_l[3 * FPD * FPD];

// ---------------------------------------------------------------------------
// Helpers
// ---------------------------------------------------------------------------
__device__ __forceinline__ uint32_t s2u(const void* p) {
    uint32_t a;
    asm("{ .reg .u64 t; cvta.to.shared.u64 t, %1; cvt.u32.u64 %0, t; }" : "=r"(a) : "l"(p));
    return a;
}
__device__ __forceinline__ void mma16816(float* c, const uint32_t* a, const uint32_t* b) {
    asm volatile("mma.sync.aligned.m16n8k16.row.col.f32.bf16.bf16.f32 "
        "{%0,%1,%2,%3}, {%4,%5,%6,%7}, {%8,%9}, {%0,%1,%2,%3};"
        : "+f"(c[0]), "+f"(c[1]), "+f"(c[2]), "+f"(c[3])
        : "r"(a[0]), "r"(a[1]), "r"(a[2]), "r"(a[3]), "r"(b[0]), "r"(b[1]));
}
__device__ __forceinline__ void ldm4(uint32_t* r, uint32_t addr) {
    asm volatile("ldmatrix.sync.aligned.m8n8.x4.shared.b16 {%0,%1,%2,%3}, [%4];"
        : "=r"(r[0]), "=r"(r[1]), "=r"(r[2]), "=r"(r[3]) : "r"(addr));
}
__device__ __forceinline__ void cpa16(uint32_t d, const void* s) {
    asm volatile("cp.async.cg.shared.global [%0], [%1], 16;" :: "r"(d), "l"(s) : "memory");
}
#define CP_COMMIT() asm volatile("cp.async.commit_group;" ::: "memory")
#define CP_WAIT1()  asm volatile("cp.async.wait_group 1;" ::: "memory")
#define CP_WAIT0()  asm volatile("cp.async.wait_group 0;" ::: "memory")

__device__ __forceinline__ float leakyf(float x) { return x > 0.f ? x : 0.01f * x; }
__device__ __forceinline__ float sigmf(float x)  { return 1.f / (1.f + expf(-x)); }
__device__ __forceinline__ void split2(float v, __nv_bfloat16& h, __nv_bfloat16& l) {
    h = __float2bfloat16(v);
    l = __float2bfloat16(v - __bfloat162float(h));
}
__device__ __forceinline__ uint32_t pk2(__nv_bfloat16 a, __nv_bfloat16 b) {
    return (uint32_t)__bfloat16_as_ushort(a) | ((uint32_t)__bfloat16_as_ushort(b) << 16);
}

// ---------------------------------------------------------------------------
// Kernel 0: split weights to bf16 hi/lo pairs
// ---------------------------------------------------------------------------
__global__ void prep_w(const float* __restrict__ Wat, const float* __restrict__ Wih,
                       const float* __restrict__ Whh) {
    int i = blockIdx.x * 256 + threadIdx.x;
    if (i < FPD * FPD)     split2(Wat[i], g_Wat_h[i], g_Wat_l[i]);
    if (i < 3 * FPD * FPD) {
        split2(Wih[i], g_Wih_h[i], g_Wih_l[i]);
        split2(Whh[i], g_Whh_h[i], g_Whh_l[i]);
    }
}

// ---------------------------------------------------------------------------
// Kernel 1: attn — weights now REGISTER-resident (thread f owns its 88 weights);
// activations broadcast from smem. Dataflow otherwise identical to R7 (passing).
// ---------------------------------------------------------------------------
#define K1_ATOMS 32
#define O_ACTS 0                         // [12][56]
#define O_AROW (O_ACTS + 12 * 56)        // [2][40]
#define O_RED  (O_AROW + 80)             // [8][14]
#define O_PADF (O_RED + 112)             // [12]
#define O_IDX  (O_PADF + 12)             // [24] ints
#define K1_SMEM ((O_IDX + 24) * 4)

__global__ void __launch_bounds__(256) attn_kernel(
    const float* __restrict__ atom_list, const float* __restrict__ bond_list,
    const int*   __restrict__ adeg,      const int*   __restrict__ bdeg,
    const float* __restrict__ W_atom,    const float* __restrict__ b_atom,
    const float* __restrict__ W_nbr,     const float* __restrict__ b_nbr,
    const float* __restrict__ W_align,   const float* __restrict__ b_align)
{
    extern __shared__ float smem[];
    float* acts = smem + O_ACTS;
    float* arow = smem + O_AROW;
    float* red  = smem + O_RED;
    float* padf = smem + O_PADF;
    int*   idx  = (int*)(smem + O_IDX);

    const int tid = threadIdx.x;
    const int f   = tid;

    // per-thread register weights
    float wa_r[AD], wn_r[CD];
    #pragma unroll
    for (int k = 0; k < AD; k++) wa_r[k] = W_atom[f * AD + k];
    #pragma unroll
    for (int k = 0; k < CD; k++) wn_r[k] = W_nbr[f * CD + k];

    const float ba   = b_atom[f];
    const float bn   = b_nbr[f];
    const float bal  = b_align[0];
    const float wal1 = W_align[f];
    const float wal2 = W_align[FPD + f];

    const int warp = tid >> 5;
    const int lane = tid & 31;
    const int base = blockIdx.x * K1_ATOMS;

    for (int ai = 0; ai < K1_ATOMS; ai += 2) {
        const int atom0 = base + ai;
        const int bmol  = atom0 / LQ;

        __syncthreads();
        if (tid < 24) {
            int a = tid / 12, j = tid % 12;
            int atom = atom0 + a;
            if (j < MQ) {
                int ia = adeg[atom * MQ + j];
                idx[a * 12 + j] = ia;
                padf[a * 6 + j] = (ia == LQ - 1) ? 1.f : 0.f;
            } else {
                idx[a * 12 + j] = bdeg[atom * MQ + (j - MQ)];
            }
        }
        __syncthreads();
        for (int i = tid; i < 2 * (AD + MQ * CD); i += 256) {
            int a = i / 333, j = i % 333;
            if (j < AD) {
                arow[a * 40 + j] = atom_list[(atom0 + a) * AD + j];
            } else {
                int m = (j - AD) / CD, c = (j - AD) % CD;
                float v;
                if (c < AD) v = atom_list[(bmol * LQ + idx[a * 12 + m]) * AD + c];
                else        v = bond_list[(bmol * LQ + idx[a * 12 + 6 + m]) * BD + (c - AD)];
                acts[(a * 6 + m) * 56 + c] = v;
            }
        }
        __syncthreads();

        // projections (weights from registers, activations broadcast from smem)
        float af[2]; af[0] = ba; af[1] = ba;
        #pragma unroll
        for (int k0 = 0; k0 < 36; k0 += 4) {
            #pragma unroll
            for (int a = 0; a < 2; a++) {
                float4 x = *(const float4*)&arow[a * 40 + k0];
                af[a] += wa_r[k0] * x.x + wa_r[k0 + 1] * x.y
                       + wa_r[k0 + 2] * x.z + wa_r[k0 + 3] * x.w;
            }
        }
        #pragma unroll
        for (int a = 0; a < 2; a++)
            af[a] += wa_r[36] * arow[a * 40 + 36] + wa_r[37] * arow[a * 40 + 37]
                   + wa_r[38] * arow[a * 40 + 38];
        af[0] = leakyf(af[0]); af[1] = leakyf(af[1]);

        float nf[2][MQ];
        #pragma unroll
        for (int a = 0; a < 2; a++)
            #pragma unroll
            for (int m = 0; m < MQ; m++) nf[a][m] = bn;
        #pragma unroll
        for (int k0 = 0; k0 < 48; k0 += 4) {
            #pragma unroll
            for (int a = 0; a < 2; a++)
                #pragma unroll
                for (int m = 0; m < MQ; m++) {
                    float4 x = *(const float4*)&acts[(a * 6 + m) * 56 + k0];
                    nf[a][m] += wn_r[k0] * x.x + wn_r[k0 + 1] * x.y
                              + wn_r[k0 + 2] * x.z + wn_r[k0 + 3] * x.w;
                }
        }
        #pragma unroll
        for (int a = 0; a < 2; a++)
            #pragma unroll
            for (int m = 0; m < MQ; m++)
                nf[a][m] += wn_r[48] * acts[(a * 6 + m) * 56 + 48];
        #pragma unroll
        for (int a = 0; a < 2; a++)
            #pragma unroll
            for (int m = 0; m < MQ; m++) nf[a][m] = leakyf(nf[a][m]);

        // cross-feature dot products
        float v[14];
        #pragma unroll
        for (int a = 0; a < 2; a++) {
            v[a * 7] = af[a] * wal1;
            #pragma unroll
            for (int m = 0; m < MQ; m++) v[a * 7 + 1 + m] = nf[a][m] * wal2;
        }
        #pragma unroll
        for (int off = 16; off > 0; off >>= 1)
            #pragma unroll
            for (int j = 0; j < 14; j++)
                v[j] += __shfl_down_sync(0xffffffffu, v[j], off);
        if (lane == 0)
            #pragma unroll
            for (int j = 0; j < 14; j++) red[warp * 14 + j] = v[j];
        __syncthreads();

        // softmax + outputs
        #pragma unroll
        for (int a = 0; a < 2; a++) {
            float sums[7];
            #pragma unroll
            for (int j = 0; j < 7; j++) {
                float s = 0.f;
                #pragma unroll
                for (int w = 0; w < 8; w++) s += red[w * 14 + a * 7 + j];
                sums[j] = s;
            }
            float sc[MQ], mx = -INFINITY;
            #pragma unroll
            for (int m = 0; m < MQ; m++) {
                float s = leakyf(sums[0] + sums[1 + m] + bal);
                if (padf[a * 6 + m] > 0.5f) s += -9e8f;
                sc[m] = s;
                mx = fmaxf(mx, s);
            }
            float e[MQ], se = 0.f;
            #pragma unroll
            for (int m = 0; m < MQ; m++) { e[m] = expf(sc[m] - mx); se += e[m]; }
            float inv = 1.f / se;
            float asum = 0.f, sf = 0.f;
            #pragma unroll
            for (int m = 0; m < MQ; m++) {
                float aw = e[m] * inv;
                if (padf[a * 6 + m] > 0.5f) aw = 0.f;
                asum += aw;
                sf   += aw * nf[a][m];
            }
            const int atom = atom0 + a;
            const int o = atom * FPD + f;
            g_af[o] = af[a];
            split2(af[a], g_af_hi[o], g_af_lo[o]);
            split2(sf,    g_s_hi[o],  g_s_lo[o]);
            if (tid == 0) g_asum[atom] = asum;
        }
    }
}

// ---------------------------------------------------------------------------
// Kernel 2a: ctx = elu( s @ W_att^T + asum*b ), mma.sync + ldmatrix (R7 version)
// ---------------------------------------------------------------------------
#define CTX_AH 0
#define CTX_AL 10240
#define CTX_BH 20480
#define CTX_BL 25600
#define CTX_BUF 30720
#define CTX_BATT (2 * CTX_BUF)
#define CTX_SMEM (CTX_BATT + 256)

__global__ void __launch_bounds__(256) ctx_mma(const float* __restrict__ batt_g)
{
    extern __shared__ char sm[];
    const uint32_t sb = s2u(sm);
    float* sbatt = (float*)(sm + CTX_BATT);
    const int tid = threadIdx.x, wid = tid >> 5, lane = tid & 31;
    const int m0 = blockIdx.x * 128, n0 = blockIdx.y * 64;
    const int Moff = (wid & 3) * 32, Noff = (wid >> 2) * 32;

    if (tid < 64) sbatt[tid] = batt_g[n0 + tid];

    const int r_ = tid >> 2, q_ = tid & 3;
    const uint32_t soff = (uint32_t)(r_ * 80 + q_ * 16);
    const int aoff0 = (m0 + r_) * FPD + q_ * 8;
    const int aoff1 = (m0 + 64 + r_) * FPD + q_ * 8;
    const int boff  = (n0 + r_) * FPD + q_ * 8;

    const uint32_t a_lo = (uint32_t)((lane & 15) * 80 + (lane >> 4) * 16);
    const uint32_t b_lo = (uint32_t)(((lane & 7) + ((lane >> 4) << 3)) * 80 + ((lane >> 3) & 1) * 16);

    const int row0 = lane >> 2, qb = lane & 3;
    float acc[2][4][4] = {};

    cpa16(sb + CTX_AH + soff,        g_s_hi + aoff0);
    cpa16(sb + CTX_AH + 5120 + soff, g_s_hi + aoff1);
    cpa16(sb + CTX_AL + soff,        g_s_lo + aoff0);
    cpa16(sb + CTX_AL + 5120 + soff, g_s_lo + aoff1);
    cpa16(sb + CTX_BH + soff, g_Wat_h + boff);
    cpa16(sb + CTX_BL + soff, g_Wat_l + boff);
    CP_COMMIT();

    for (int c = 0; c < 8; c++) {
        if (c < 7) {
            const int k0 = (c + 1) * 32;
            const uint32_t bo = ((c + 1) & 1) * CTX_BUF;
            cpa16(sb + bo + CTX_AH + soff,        g_s_hi + aoff0 + k0);
            cpa16(sb + bo + CTX_AH + 5120 + soff, g_s_hi + aoff1 + k0);
            cpa16(sb + bo + CTX_AL + soff,        g_s_lo + aoff0 + k0);
            cpa16(sb + bo + CTX_AL + 5120 + soff, g_s_lo + aoff1 + k0);
            cpa16(sb + bo + CTX_BH + soff, g_Wat_h + boff + k0);
            cpa16(sb + bo + CTX_BL + soff, g_Wat_l + boff + k0);
            CP_COMMIT();
            CP_WAIT1();
        } else {
            CP_WAIT0();
        }
        __syncthreads();
        const uint32_t bb = sb + (c & 1) * CTX_BUF;
        #pragma unroll
        for (int ks = 0; ks < 2; ks++) {
            uint32_t ah[2][4], al[2][4];
            #pragma unroll
            for (int mt = 0; mt < 2; mt++) {
                uint32_t ao = (uint32_t)((Moff + mt * 16) * 80) + a_lo + ks * 32;
                ldm4(ah[mt], bb + CTX_AH + ao);
                ldm4(al[mt], bb + CTX_AL + ao);
            }
            uint32_t bh[2][4], bl[2][4];
            #pragma unroll
            for (int p = 0; p < 2; p++) {
                uint32_t bo2 = (uint32_t)((Noff + p * 16) * 80) + b_lo + ks * 32;
                ldm4(bh[p], bb + CTX_BH + bo2);
                ldm4(bl[p], bb + CTX_BL + bo2);
            }
            #pragma unroll
            for (int mt = 0; mt < 2; mt++)
                #pragma unroll
                for (int nt = 0; nt < 4; nt++) {
                    const uint32_t* Bh = &bh[nt >> 1][(nt & 1) * 2];
                    const uint32_t* Bl = &bl[nt >> 1][(nt & 1) * 2];
                    mma16816(acc[mt][nt], ah[mt], Bh);
                    mma16816(acc[mt][nt], ah[mt], Bl);
                    mma16816(acc[mt][nt], al[mt], Bh);
                }
        }
        __syncthreads();
    }

    #pragma unroll
    for (int mt = 0; mt < 2; mt++) {
        int r0 = m0 + Moff + mt * 16 + row0;
        float as0 = g_asum[r0], as1 = g_asum[r0 + 8];
        #pragma unroll
        for (int nt = 0; nt < 4; nt++) {
            int cl = Noff + nt * 8 + qb * 2;
            int col = n0 + cl;
            float b0 = sbatt[cl], b1 = sbatt[cl + 1];
            float t00 = acc[mt][nt][0] + as0 * b0, t01 = acc[mt][nt][1] + as0 * b1;
            float t10 = acc[mt][nt][2] + as1 * b0, t11 = acc[mt][nt][3] + as1 * b1;
            t00 = t00 > 0.f ? t00 : expm1f(t00);
            t01 = t01 > 0.f ? t01 : expm1f(t01);
            t10 = t10 > 0.f ? t10 : expm1f(t10);
            t11 = t11 > 0.f ? t11 : expm1f(t11);
            __nv_bfloat16 h0, l0, h1, l1;
            split2(t00, h0, l0); split2(t01, h1, l1);
            *(uint32_t*)&g_cx_hi[r0 * FPD + col] = pk2(h0, h1);
            *(uint32_t*)&g_cx_lo[r0 * FPD + col] = pk2(l0, l1);
            split2(t10, h0, l0); split2(t11, h1, l1);
            *(uint32_t*)&g_cx_hi[(r0 + 8) * FPD + col] = pk2(h0, h1);
            *(uint32_t*)&g_cx_lo[(r0 + 8) * FPD + col] = pk2(l0, l1);
        }
    }
}

// ---------------------------------------------------------------------------
// Kernel 2b: GRU — CTA 256 thr (8 warps, 4M x 2N), M=64 x N=32, KC=32.
// Stage 51.2KB, double-buffer -> 2 CTAs/SM (regs 82, smem 103KB/CTA).
// Tiles: A: 0 cx_hi, 1 cx_lo, 2 af_hi, 3 af_lo (64rows x 80B);
//        B at +20480: tile (2g+half) 32rows x 80B per gate g hi/lo.
// ---------------------------------------------------------------------------
#define GTA     5120                 // 64 x 80
#define GTB     2560                 // 32 x 80
#define GB_B    (4 * GTA)            // 20480
#define GB_BUF  (GB_B + 12 * GTB)    // 51200
#define GB_BIAS (2 * GB_BUF)         // 102400: float[192]
#define GB_SMEM (GB_BIAS + 768 + 32)

__global__ void __launch_bounds__(256) gru_mma(
    const float* __restrict__ b_ih, const float* __restrict__ b_hh,
    float* __restrict__ out)
{
    extern __shared__ char sm[];
    const uint32_t sb = s2u(sm);
    float* sbias = (float*)(sm + GB_BIAS);
    const int tid = threadIdx.x, wid = tid >> 5, lane = tid & 31;
    const int m0 = blockIdx.x * 64, f0 = blockIdx.y * 32;
    const int Moff = (wid >> 1) * 16, Noff = (wid & 1) * 16;

    if (tid < 192) {
        int g = tid >> 5, fl = tid & 31;
        sbias[tid] = (g < 3) ? b_ih[g * FPD + f0 + fl] : b_hh[(g - 3) * FPD + f0 + fl];
    }

    // staging maps
    const int rA = tid >> 2;             // 0..63
    const int half = tid >> 7;           // 0 hi, 1 lo (for B tiles)
    const int rB = (tid >> 2) & 31;      // 0..31
    const int sg = tid & 3;              // 16B segment
    const uint32_t aoffS = (uint32_t)(rA * 80 + sg * 16);
    const uint32_t boffS = (uint32_t)(rB * 80 + sg * 16);
    const int aRow  = (m0 + rA) * FPD + sg * 8;
    const int bRow0 = (0 * FPD + f0 + rB) * FPD + sg * 8;
    const int bRow1 = (1 * FPD + f0 + rB) * FPD + sg * 8;
    const int bRow2 = (2 * FPD + f0 + rB) * FPD + sg * 8;

    const __nv_bfloat16* srcA[4] = { g_cx_hi, g_cx_lo, g_af_hi, g_af_lo };
    const __nv_bfloat16* srcB[6] = {
        half ? g_Wih_l : g_Wih_h, half ? g_Wih_l : g_Wih_h, half ? g_Wih_l : g_Wih_h,
        half ? g_Whh_l : g_Whh_h, half ? g_Whh_l : g_Whh_h, half ? g_Whh_l : g_Whh_h };
    const int bRow[6] = { bRow0, bRow1, bRow2, bRow0, bRow1, bRow2 };

    const uint32_t a_lo = (uint32_t)((lane & 15) * 80 + (lane >> 4) * 16);
    const uint32_t b_lo = (uint32_t)(((lane & 7) + ((lane >> 4) << 3)) * 80 + ((lane >> 3) & 1) * 16);

    const int row0 = lane >> 2, qb = lane & 3;
    float acc[6][2][4] = {};

    // prologue: stage chunk 0
    #pragma unroll
    for (int t = 0; t < 4; t++) cpa16(sb + (uint32_t)(t * GTA) + aoffS, srcA[t] + aRow);
    #pragma unroll
    for (int g = 0; g < 6; g++)
        cpa16(sb + GB_B + (uint32_t)((2 * g + half) * GTB) + boffS, srcB[g] + bRow[g]);
    CP_COMMIT();

    for (int c = 0; c < 8; c++) {
        if (c < 7) {
            const int k0 = (c + 1) * 32;
            const uint32_t bs = sb + ((c + 1) & 1) * GB_BUF;
            #pragma unroll
            for (int t = 0; t < 4; t++)
                cpa16(bs + (uint32_t)(t * GTA) + aoffS, srcA[t] + aRow + k0);
            #pragma unroll
            for (int g = 0; g < 6; g++)
                cpa16(bs + GB_B + (uint32_t)((2 * g + half) * GTB) + boffS, srcB[g] + bRow[g] + k0);
            CP_COMMIT();
            CP_WAIT1();
        } else {
            CP_WAIT0();
        }
        __syncthreads();
        const uint32_t bb = sb + (c & 1) * GB_BUF;
        #pragma unroll
        for (int ks = 0; ks < 2; ks++) {
            uint32_t Ah[2][4], Al[2][4];   // [am: 0=ctx 1=af]
            #pragma unroll
            for (int am = 0; am < 2; am++) {
                uint32_t ao = (uint32_t)(Moff * 80) + a_lo + ks * 32;
                ldm4(Ah[am], bb + (uint32_t)((am * 2) * GTA) + ao);
                ldm4(Al[am], bb + (uint32_t)((am * 2 + 1) * GTA) + ao);
            }
            #pragma unroll
            for (int g = 0; g < 6; g++) {
                uint32_t bhf[4], blf[4];
                uint32_t bo2 = (uint32_t)(Noff * 80) + b_lo + ks * 32;
                ldm4(bhf, bb + GB_B + (uint32_t)((2 * g) * GTB) + bo2);
                ldm4(blf, bb + GB_B + (uint32_t)((2 * g + 1) * GTB) + bo2);
                const int am = (g < 3) ? 0 : 1;
                #pragma unroll
                for (int nt = 0; nt < 2; nt++) {
                    const uint32_t* Bh = &bhf[nt * 2];
                    const uint32_t* Bl = &blf[nt * 2];
                    mma16816(acc[g][nt], Ah[am], Bh);
                    mma16816(acc[g][nt], Ah[am], Bl);
                    mma16816(acc[g][nt], Al[am], Bh);
                }
            }
        }
        __syncthreads();
    }

    // fused GRU + ReLU epilogue (0=i_r 1=i_z 2=i_n 3=h_r 4=h_z 5=h_n)
    #pragma unroll
    for (int rp = 0; rp < 2; rp++) {
        int row = m0 + Moff + row0 + rp * 8;
        #pragma unroll
        for (int nt = 0; nt < 2; nt++) {
            int cl = Noff + nt * 8 + qb * 2;
            int colG = f0 + cl;
            float o2[2];
            #pragma unroll
            for (int j = 0; j < 2; j++) {
                int ci = rp * 2 + j;
                float ir  = acc[0][nt][ci] + sbias[cl + j];
                float iz  = acc[1][nt][ci] + sbias[32 + cl + j];
                float in_ = acc[2][nt][ci] + sbias[64 + cl + j];
                float hr  = acc[3][nt][ci] + sbias[96 + cl + j];
                float hz  = acc[4][nt][ci] + sbias[128 + cl + j];
                float hn  = acc[5][nt][ci] + sbias[160 + cl + j];
                float r = sigmf(ir + hr), z = sigmf(iz + hz);
                float n = tanhf(in_ + r * hn);
                float h = g_af[row * FPD + colG + j];
                o2[j] = fmaxf((1.f - z) * n + z * h, 0.f);
            }
            *(float2*)&out[row * FPD + colG] = make_float2(o2[0], o2[1]);
        }
    }
}

// ---------------------------------------------------------------------------
// Launcher
// ---------------------------------------------------------------------------
extern "C" void kernel_launch(void* const* d_in, const int* in_sizes, int n_in,
                              void* d_out, int out_size)
{
    const float* atom_list = (const float*)d_in[0];
    const float* bond_list = (const float*)d_in[1];
    const int*   adeg      = (const int*)  d_in[2];
    const int*   bdeg      = (const int*)  d_in[3];
    const float* W_atom   = (const float*)d_in[5];
    const float* b_atom   = (const float*)d_in[6];
    const float* W_nbr    = (const float*)d_in[7];
    const float* b_nbr    = (const float*)d_in[8];
    const float* W_align  = (const float*)d_in[9];
    const float* b_align  = (const float*)d_in[10];
    const float* W_attend = (const float*)d_in[11];
    const float* b_attend = (const float*)d_in[12];
    const float* W_ih     = (const float*)d_in[13];
    const float* b_ih     = (const float*)d_in[14];
    const float* W_hh     = (const float*)d_in[15];
    const float* b_hh     = (const float*)d_in[16];
    float* out = (float*)d_out;
    (void)in_sizes; (void)n_in; (void)out_size;

    cudaFuncSetAttribute(attn_kernel, cudaFuncAttributeMaxDynamicSharedMemorySize, K1_SMEM);
    cudaFuncSetAttribute(ctx_mma,     cudaFuncAttributeMaxDynamicSharedMemorySize, CTX_SMEM);
    cudaFuncSetAttribute(gru_mma,     cudaFuncAttributeMaxDynamicSharedMemorySize, GB_SMEM);

    prep_w<<<(3 * FPD * FPD + 255) / 256, 256>>>(W_attend, W_ih, W_hh);

    attn_kernel<<<NATOMS / K1_ATOMS, 256, K1_SMEM>>>(
        atom_list, bond_list, adeg, bdeg,
        W_atom, b_atom, W_nbr, b_nbr, W_align, b_align);

    dim3 gc(NATOMS / 128, FPD / 64);
    ctx_mma<<<gc, 256, CTX_SMEM>>>(b_attend);

    dim3 gg(NATOMS / 64, FPD / 32);
    gru_mma<<<gg, 256, GB_SMEM>>>(b_ih, b_hh, out);
}

// round 9
// speedup vs baseline: 1.4559x; 1.4559x over previous
#include <cuda_runtime.h>
#include <cuda_bf16.h>
#include <math.h>
#include <stdint.h>

// Problem constants
#define BQ   512
#define LQ   128
#define MQ   6
#define AD   39
#define BD   10
#define CD   49
#define FPD  256
#define NATOMS (BQ * LQ)   // 65536

// ---------------------------------------------------------------------------
// Device-global scratch (allocation-free rule)
// ---------------------------------------------------------------------------
__device__ __align__(16) float g_af[NATOMS * FPD];
__device__ __align__(16) float g_PA[NATOMS * FPD];   // atom part of nbr proj
__device__ __align__(16) float g_PB[NATOMS * FPD];   // bond part of nbr proj
__device__ __align__(16) float g_asum[NATOMS];
__device__ __align__(16) __nv_bfloat16 g_s_hi[NATOMS * FPD],  g_s_lo[NATOMS * FPD];
__device__ __align__(16) __nv_bfloat16 g_af_hi[NATOMS * FPD], g_af_lo[NATOMS * FPD];
__device__ __align__(16) __nv_bfloat16 g_cx_hi[NATOMS * FPD], g_cx_lo[NATOMS * FPD];
__device__ __align__(16) __nv_bfloat16 g_Wat_h[FPD * FPD],     g_Wat_l[FPD * FPD];
__device__ __align__(16) __nv_bfloat16 g_Wih_h[3 * FPD * FPD], g_Wih_l[3 * FPD * FPD];
__device__ __align__(16) __nv_bfloat16 g_Whh_h[3 * FPD * FPD], g_Whh_l[3 * FPD * FPD];

// ---------------------------------------------------------------------------
// Helpers
// ---------------------------------------------------------------------------
__device__ __forceinline__ uint32_t s2u(const void* p) {
    uint32_t a;
    asm("{ .reg .u64 t; cvta.to.shared.u64 t, %1; cvt.u32.u64 %0, t; }" : "=r"(a) : "l"(p));
    return a;
}
__device__ __forceinline__ void mma16816(float* c, const uint32_t* a, const uint32_t* b) {
    asm volatile("mma.sync.aligned.m16n8k16.row.col.f32.bf16.bf16.f32 "
        "{%0,%1,%2,%3}, {%4,%5,%6,%7}, {%8,%9}, {%0,%1,%2,%3};"
        : "+f"(c[0]), "+f"(c[1]), "+f"(c[2]), "+f"(c[3])
        : "r"(a[0]), "r"(a[1]), "r"(a[2]), "r"(a[3]), "r"(b[0]), "r"(b[1]));
}
__device__ __forceinline__ void ldm4(uint32_t* r, uint32_t addr) {
    asm volatile("ldmatrix.sync.aligned.m8n8.x4.shared.b16 {%0,%1,%2,%3}, [%4];"
        : "=r"(r[0]), "=r"(r[1]), "=r"(r[2]), "=r"(r[3]) : "r"(addr));
}
__device__ __forceinline__ void cpa16(uint32_t d, const void* s) {
    asm volatile("cp.async.cg.shared.global [%0], [%1], 16;" :: "r"(d), "l"(s) : "memory");
}
#define CP_COMMIT() asm volatile("cp.async.commit_group;" ::: "memory")
#define CP_WAIT1()  asm volatile("cp.async.wait_group 1;" ::: "memory")
#define CP_WAIT0()  asm volatile("cp.async.wait_group 0;" ::: "memory")

__device__ __forceinline__ float leakyf(float x) { return x > 0.f ? x : 0.01f * x; }
__device__ __forceinline__ float sigmf(float x)  { return 1.f / (1.f + expf(-x)); }
__device__ __forceinline__ void split2(float v, __nv_bfloat16& h, __nv_bfloat16& l) {
    h = __float2bfloat16(v);
    l = __float2bfloat16(v - __bfloat162float(h));
}
__device__ __forceinline__ uint32_t pk2(__nv_bfloat16 a, __nv_bfloat16 b) {
    return (uint32_t)__bfloat16_as_ushort(a) | ((uint32_t)__bfloat16_as_ushort(b) << 16);
}

// ---------------------------------------------------------------------------
// Kernel 0: split weights to bf16 hi/lo pairs
// ---------------------------------------------------------------------------
__global__ void prep_w(const float* __restrict__ Wat, const float* __restrict__ Wih,
                       const float* __restrict__ Whh) {
    int i = blockIdx.x * 256 + threadIdx.x;
    if (i < FPD * FPD)     split2(Wat[i], g_Wat_h[i], g_Wat_l[i]);
    if (i < 3 * FPD * FPD) {
        split2(Wih[i], g_Wih_h[i], g_Wih_l[i]);
        split2(Whh[i], g_Whh_h[i], g_Whh_l[i]);
    }
}

// ---------------------------------------------------------------------------
// Kernel 1a: per-position projections.
//   af = leaky(atom @ W_atom^T + b_atom)   (+ bf16 splits)
//   PA = atom @ WnA^T   (W_nbr cols 0..38, NO bias/leaky)
//   PB = bond @ WnB^T   (W_nbr cols 39..48)
// Thread = feature; 64 atoms/CTA; weights transposed in smem; 8-atom batches.
// ---------------------------------------------------------------------------
#define PJ_ATOMS 64
#define PJ_WA  0
#define PJ_WNA (AD * FPD)                // 9984
#define PJ_WNB (PJ_WNA + AD * FPD)       // 19968
#define PJ_AR  (PJ_WNB + BD * FPD)       // 22528  [8][40]
#define PJ_BR  (PJ_AR + 8 * 40)          // 22848  [8][12]
#define PJ_SMEM ((PJ_BR + 8 * 12) * 4)   // 91776 B

__global__ void __launch_bounds__(256, 2) proj_kernel(
    const float* __restrict__ atom_list, const float* __restrict__ bond_list,
    const float* __restrict__ W_atom,    const float* __restrict__ b_atom,
    const float* __restrict__ W_nbr)
{
    extern __shared__ float smem[];
    float* Wa   = smem + PJ_WA;
    float* WnA  = smem + PJ_WNA;
    float* WnB  = smem + PJ_WNB;
    float* arow = smem + PJ_AR;
    float* brow = smem + PJ_BR;

    const int tid = threadIdx.x;
    const int f   = tid;

    for (int i = tid; i < AD * FPD; i += 256) {
        int ff = i / AD, k = i % AD;
        Wa[k * FPD + ff]  = W_atom[ff * AD + k];
        WnA[k * FPD + ff] = W_nbr[ff * CD + k];
    }
    for (int i = tid; i < BD * FPD; i += 256) {
        int ff = i / BD, k = i % BD;
        WnB[k * FPD + ff] = W_nbr[ff * CD + AD + k];
    }
    const float ba = b_atom[f];
    __syncthreads();

    const int base = blockIdx.x * PJ_ATOMS;

    for (int ab = 0; ab < PJ_ATOMS; ab += 8) {
        const int atom0 = base + ab;
        __syncthreads();
        // stage 8 atom rows (39) + bond rows (10)
        for (int i = tid; i < 8 * 49; i += 256) {
            int a = i / 49, j = i % 49;
            if (j < AD) arow[a * 40 + j] = atom_list[(atom0 + a) * AD + j];
            else        brow[a * 12 + (j - AD)] = bond_list[(atom0 + a) * BD + (j - AD)];
        }
        __syncthreads();

        float af8[8], pa8[8], pb8[8];
        #pragma unroll
        for (int a = 0; a < 8; a++) { af8[a] = ba; pa8[a] = 0.f; pb8[a] = 0.f; }

        // atom part: k = 0..35 in groups of 4, then 36..38
        #pragma unroll
        for (int k0 = 0; k0 < 36; k0 += 4) {
            float wa0 = Wa[(k0 + 0) * FPD + f], wa1 = Wa[(k0 + 1) * FPD + f];
            float wa2 = Wa[(k0 + 2) * FPD + f], wa3 = Wa[(k0 + 3) * FPD + f];
            float wn0 = WnA[(k0 + 0) * FPD + f], wn1 = WnA[(k0 + 1) * FPD + f];
            float wn2 = WnA[(k0 + 2) * FPD + f], wn3 = WnA[(k0 + 3) * FPD + f];
            #pragma unroll
            for (int a = 0; a < 8; a++) {
                float4 x = *(const float4*)&arow[a * 40 + k0];
                af8[a] += wa0 * x.x + wa1 * x.y + wa2 * x.z + wa3 * x.w;
                pa8[a] += wn0 * x.x + wn1 * x.y + wn2 * x.z + wn3 * x.w;
            }
        }
        {
            float wa0 = Wa[36 * FPD + f], wa1 = Wa[37 * FPD + f], wa2 = Wa[38 * FPD + f];
            float wn0 = WnA[36 * FPD + f], wn1 = WnA[37 * FPD + f], wn2 = WnA[38 * FPD + f];
            #pragma unroll
            for (int a = 0; a < 8; a++) {
                float x0 = arow[a * 40 + 36], x1 = arow[a * 40 + 37], x2 = arow[a * 40 + 38];
                af8[a] += wa0 * x0 + wa1 * x1 + wa2 * x2;
                pa8[a] += wn0 * x0 + wn1 * x1 + wn2 * x2;
            }
        }
        // bond part: k = 0..7 groups of 4, then 8..9
        #pragma unroll
        for (int k0 = 0; k0 < 8; k0 += 4) {
            float wb0 = WnB[(k0 + 0) * FPD + f], wb1 = WnB[(k0 + 1) * FPD + f];
            float wb2 = WnB[(k0 + 2) * FPD + f], wb3 = WnB[(k0 + 3) * FPD + f];
            #pragma unroll
            for (int a = 0; a < 8; a++) {
                float4 x = *(const float4*)&brow[a * 12 + k0];
                pb8[a] += wb0 * x.x + wb1 * x.y + wb2 * x.z + wb3 * x.w;
            }
        }
        {
            float wb0 = WnB[8 * FPD + f], wb1 = WnB[9 * FPD + f];
            #pragma unroll
            for (int a = 0; a < 8; a++)
                pb8[a] += wb0 * brow[a * 12 + 8] + wb1 * brow[a * 12 + 9];
        }

        #pragma unroll
        for (int a = 0; a < 8; a++) {
            const int o = (atom0 + a) * FPD + f;
            float afv = leakyf(af8[a]);
            g_af[o] = afv;
            split2(afv, g_af_hi[o], g_af_lo[o]);
            g_PA[o] = pa8[a];
            g_PB[o] = pb8[a];
        }
    }
}

// ---------------------------------------------------------------------------
// Kernel 1b: attention — nf from gathered PA/PB rows, softmax, weighted sum.
// Thread = feature; 32 atoms/CTA, 2 per iteration. Reduction code from the
// proven R6/R7 kernel, verbatim.
// ---------------------------------------------------------------------------
#define B_ATOMS 32

__global__ void __launch_bounds__(256) attn2_kernel(
    const int*   __restrict__ adeg,    const int*   __restrict__ bdeg,
    const float* __restrict__ b_nbr,   const float* __restrict__ W_align,
    const float* __restrict__ b_align)
{
    __shared__ float red[112];   // [8][14]
    __shared__ float padf[12];
    __shared__ int   idx[24];

    const int tid = threadIdx.x;
    const int f   = tid;
    const float bn   = b_nbr[f];
    const float bal  = b_align[0];
    const float wal1 = W_align[f];
    const float wal2 = W_align[FPD + f];

    const int warp = tid >> 5;
    const int lane = tid & 31;
    const int base = blockIdx.x * B_ATOMS;

    for (int ai = 0; ai < B_ATOMS; ai += 2) {
        const int atom0 = base + ai;
        const int bmol  = atom0 / LQ;

        __syncthreads();
        if (tid < 24) {
            int a = tid / 12, j = tid % 12;
            int atom = atom0 + a;
            if (j < MQ) {
                int ia = adeg[atom * MQ + j];
                idx[a * 12 + j] = ia;
                padf[a * 6 + j] = (ia == LQ - 1) ? 1.f : 0.f;
            } else {
                idx[a * 12 + j] = bdeg[atom * MQ + (j - MQ)];
            }
        }
        __syncthreads();

        float nfs[2][MQ];
        float v[14];
        #pragma unroll
        for (int a = 0; a < 2; a++) {
            const int atom = atom0 + a;
            float afv = g_af[atom * FPD + f];
            v[a * 7] = afv * wal1;
            #pragma unroll
            for (int m = 0; m < MQ; m++) {
                int ja = bmol * LQ + idx[a * 12 + m];
                int jb = bmol * LQ + idx[a * 12 + 6 + m];
                float t = leakyf(g_PA[ja * FPD + f] + g_PB[jb * FPD + f] + bn);
                nfs[a][m] = t;
                v[a * 7 + 1 + m] = t * wal2;
            }
        }
        #pragma unroll
        for (int off = 16; off > 0; off >>= 1)
            #pragma unroll
            for (int j = 0; j < 14; j++)
                v[j] += __shfl_down_sync(0xffffffffu, v[j], off);
        if (lane == 0)
            #pragma unroll
            for (int j = 0; j < 14; j++) red[warp * 14 + j] = v[j];
        __syncthreads();

        #pragma unroll
        for (int a = 0; a < 2; a++) {
            float sums[7];
            #pragma unroll
            for (int j = 0; j < 7; j++) {
                float s = 0.f;
                #pragma unroll
                for (int w = 0; w < 8; w++) s += red[w * 14 + a * 7 + j];
                sums[j] = s;
            }
            float sc[MQ], mx = -INFINITY;
            #pragma unroll
            for (int m = 0; m < MQ; m++) {
                float s = leakyf(sums[0] + sums[1 + m] + bal);
                if (padf[a * 6 + m] > 0.5f) s += -9e8f;
                sc[m] = s;
                mx = fmaxf(mx, s);
            }
            float e[MQ], se = 0.f;
            #pragma unroll
            for (int m = 0; m < MQ; m++) { e[m] = expf(sc[m] - mx); se += e[m]; }
            float inv = 1.f / se;
            float asum = 0.f, sf = 0.f;
            #pragma unroll
            for (int m = 0; m < MQ; m++) {
                float aw = e[m] * inv;
                if (padf[a * 6 + m] > 0.5f) aw = 0.f;
                asum += aw;
                sf   += aw * nfs[a][m];
            }
            const int atom = atom0 + a;
            const int o = atom * FPD + f;
            split2(sf, g_s_hi[o], g_s_lo[o]);
            if (tid == 0) g_asum[atom] = asum;
        }
    }
}

// ---------------------------------------------------------------------------
// Kernel 2a: ctx = elu( s @ W_att^T + asum*b ), mma.sync + ldmatrix (unchanged)
// ---------------------------------------------------------------------------
#define CTX_AH 0
#define CTX_AL 10240
#define CTX_BH 20480
#define CTX_BL 25600
#define CTX_BUF 30720
#define CTX_BATT (2 * CTX_BUF)
#define CTX_SMEM (CTX_BATT + 256)

__global__ void __launch_bounds__(256) ctx_mma(const float* __restrict__ batt_g)
{
    extern __shared__ char sm[];
    const uint32_t sb = s2u(sm);
    float* sbatt = (float*)(sm + CTX_BATT);
    const int tid = threadIdx.x, wid = tid >> 5, lane = tid & 31;
    const int m0 = blockIdx.x * 128, n0 = blockIdx.y * 64;
    const int Moff = (wid & 3) * 32, Noff = (wid >> 2) * 32;

    if (tid < 64) sbatt[tid] = batt_g[n0 + tid];

    const int r_ = tid >> 2, q_ = tid & 3;
    const uint32_t soff = (uint32_t)(r_ * 80 + q_ * 16);
    const int aoff0 = (m0 + r_) * FPD + q_ * 8;
    const int aoff1 = (m0 + 64 + r_) * FPD + q_ * 8;
    const int boff  = (n0 + r_) * FPD + q_ * 8;

    const uint32_t a_lo = (uint32_t)((lane & 15) * 80 + (lane >> 4) * 16);
    const uint32_t b_lo = (uint32_t)(((lane & 7) + ((lane >> 4) << 3)) * 80 + ((lane >> 3) & 1) * 16);

    const int row0 = lane >> 2, qb = lane & 3;
    float acc[2][4][4] = {};

    cpa16(sb + CTX_AH + soff,        g_s_hi + aoff0);
    cpa16(sb + CTX_AH + 5120 + soff, g_s_hi + aoff1);
    cpa16(sb + CTX_AL + soff,        g_s_lo + aoff0);
    cpa16(sb + CTX_AL + 5120 + soff, g_s_lo + aoff1);
    cpa16(sb + CTX_BH + soff, g_Wat_h + boff);
    cpa16(sb + CTX_BL + soff, g_Wat_l + boff);
    CP_COMMIT();

    for (int c = 0; c < 8; c++) {
        if (c < 7) {
            const int k0 = (c + 1) * 32;
            const uint32_t bo = ((c + 1) & 1) * CTX_BUF;
            cpa16(sb + bo + CTX_AH + soff,        g_s_hi + aoff0 + k0);
            cpa16(sb + bo + CTX_AH + 5120 + soff, g_s_hi + aoff1 + k0);
            cpa16(sb + bo + CTX_AL + soff,        g_s_lo + aoff0 + k0);
            cpa16(sb + bo + CTX_AL + 5120 + soff, g_s_lo + aoff1 + k0);
            cpa16(sb + bo + CTX_BH + soff, g_Wat_h + boff + k0);
            cpa16(sb + bo + CTX_BL + soff, g_Wat_l + boff + k0);
            CP_COMMIT();
            CP_WAIT1();
        } else {
            CP_WAIT0();
        }
        __syncthreads();
        const uint32_t bb = sb + (c & 1) * CTX_BUF;
        #pragma unroll
        for (int ks = 0; ks < 2; ks++) {
            uint32_t ah[2][4], al[2][4];
            #pragma unroll
            for (int mt = 0; mt < 2; mt++) {
                uint32_t ao = (uint32_t)((Moff + mt * 16) * 80) + a_lo + ks * 32;
                ldm4(ah[mt], bb + CTX_AH + ao);
                ldm4(al[mt], bb + CTX_AL + ao);
            }
            uint32_t bh[2][4], bl[2][4];
            #pragma unroll
            for (int p = 0; p < 2; p++) {
                uint32_t bo2 = (uint32_t)((Noff + p * 16) * 80) + b_lo + ks * 32;
                ldm4(bh[p], bb + CTX_BH + bo2);
                ldm4(bl[p], bb + CTX_BL + bo2);
            }
            #pragma unroll
            for (int mt = 0; mt < 2; mt++)
                #pragma unroll
                for (int nt = 0; nt < 4; nt++) {
                    const uint32_t* Bh = &bh[nt >> 1][(nt & 1) * 2];
                    const uint32_t* Bl = &bl[nt >> 1][(nt & 1) * 2];
                    mma16816(acc[mt][nt], ah[mt], Bh);
                    mma16816(acc[mt][nt], ah[mt], Bl);
                    mma16816(acc[mt][nt], al[mt], Bh);
                }
        }
        __syncthreads();
    }

    #pragma unroll
    for (int mt = 0; mt < 2; mt++) {
        int r0 = m0 + Moff + mt * 16 + row0;
        float as0 = g_asum[r0], as1 = g_asum[r0 + 8];
        #pragma unroll
        for (int nt = 0; nt < 4; nt++) {
            int cl = Noff + nt * 8 + qb * 2;
            int col = n0 + cl;
            float b0 = sbatt[cl], b1 = sbatt[cl + 1];
            float t00 = acc[mt][nt][0] + as0 * b0, t01 = acc[mt][nt][1] + as0 * b1;
            float t10 = acc[mt][nt][2] + as1 * b0, t11 = acc[mt][nt][3] + as1 * b1;
            t00 = t00 > 0.f ? t00 : expm1f(t00);
            t01 = t01 > 0.f ? t01 : expm1f(t01);
            t10 = t10 > 0.f ? t10 : expm1f(t10);
            t11 = t11 > 0.f ? t11 : expm1f(t11);
            __nv_bfloat16 h0, l0, h1, l1;
            split2(t00, h0, l0); split2(t01, h1, l1);
            *(uint32_t*)&g_cx_hi[r0 * FPD + col] = pk2(h0, h1);
            *(uint32_t*)&g_cx_lo[r0 * FPD + col] = pk2(l0, l1);
            split2(t10, h0, l0); split2(t11, h1, l1);
            *(uint32_t*)&g_cx_hi[(r0 + 8) * FPD + col] = pk2(h0, h1);
            *(uint32_t*)&g_cx_lo[(r0 + 8) * FPD + col] = pk2(l0, l1);
        }
    }
}

// ---------------------------------------------------------------------------
// Kernel 2b: GRU — CTA 256 thr (8 warps, 4M x 2N), M=64 x N=32, KC=32.
// (unchanged from R8 — 630us, 2 CTAs/SM)
// ---------------------------------------------------------------------------
#define GTA     5120                 // 64 x 80
#define GTB     2560                 // 32 x 80
#define GB_B    (4 * GTA)            // 20480
#define GB_BUF  (GB_B + 12 * GTB)    // 51200
#define GB_BIAS (2 * GB_BUF)         // 102400: float[192]
#define GB_SMEM (GB_BIAS + 768 + 32)

__global__ void __launch_bounds__(256) gru_mma(
    const float* __restrict__ b_ih, const float* __restrict__ b_hh,
    float* __restrict__ out)
{
    extern __shared__ char sm[];
    const uint32_t sb = s2u(sm);
    float* sbias = (float*)(sm + GB_BIAS);
    const int tid = threadIdx.x, wid = tid >> 5, lane = tid & 31;
    const int m0 = blockIdx.x * 64, f0 = blockIdx.y * 32;
    const int Moff = (wid >> 1) * 16, Noff = (wid & 1) * 16;

    if (tid < 192) {
        int g = tid >> 5, fl = tid & 31;
        sbias[tid] = (g < 3) ? b_ih[g * FPD + f0 + fl] : b_hh[(g - 3) * FPD + f0 + fl];
    }

    const int rA = tid >> 2;
    const int half = tid >> 7;
    const int rB = (tid >> 2) & 31;
    const int sg = tid & 3;
    const uint32_t aoffS = (uint32_t)(rA * 80 + sg * 16);
    const uint32_t boffS = (uint32_t)(rB * 80 + sg * 16);
    const int aRow  = (m0 + rA) * FPD + sg * 8;
    const int bRow0 = (0 * FPD + f0 + rB) * FPD + sg * 8;
    const int bRow1 = (1 * FPD + f0 + rB) * FPD + sg * 8;
    const int bRow2 = (2 * FPD + f0 + rB) * FPD + sg * 8;

    const __nv_bfloat16* srcA[4] = { g_cx_hi, g_cx_lo, g_af_hi, g_af_lo };
    const __nv_bfloat16* srcB[6] = {
        half ? g_Wih_l : g_Wih_h, half ? g_Wih_l : g_Wih_h, half ? g_Wih_l : g_Wih_h,
        half ? g_Whh_l : g_Whh_h, half ? g_Whh_l : g_Whh_h, half ? g_Whh_l : g_Whh_h };
    const int bRow[6] = { bRow0, bRow1, bRow2, bRow0, bRow1, bRow2 };

    const uint32_t a_lo = (uint32_t)((lane & 15) * 80 + (lane >> 4) * 16);
    const uint32_t b_lo = (uint32_t)(((lane & 7) + ((lane >> 4) << 3)) * 80 + ((lane >> 3) & 1) * 16);

    const int row0 = lane >> 2, qb = lane & 3;
    float acc[6][2][4] = {};

    #pragma unroll
    for (int t = 0; t < 4; t++) cpa16(sb + (uint32_t)(t * GTA) + aoffS, srcA[t] + aRow);
    #pragma unroll
    for (int g = 0; g < 6; g++)
        cpa16(sb + GB_B + (uint32_t)((2 * g + half) * GTB) + boffS, srcB[g] + bRow[g]);
    CP_COMMIT();

    for (int c = 0; c < 8; c++) {
        if (c < 7) {
            const int k0 = (c + 1) * 32;
            const uint32_t bs = sb + ((c + 1) & 1) * GB_BUF;
            #pragma unroll
            for (int t = 0; t < 4; t++)
                cpa16(bs + (uint32_t)(t * GTA) + aoffS, srcA[t] + aRow + k0);
            #pragma unroll
            for (int g = 0; g < 6; g++)
                cpa16(bs + GB_B + (uint32_t)((2 * g + half) * GTB) + boffS, srcB[g] + bRow[g] + k0);
            CP_COMMIT();
            CP_WAIT1();
        } else {
            CP_WAIT0();
        }
        __syncthreads();
        const uint32_t bb = sb + (c & 1) * GB_BUF;
        #pragma unroll
        for (int ks = 0; ks < 2; ks++) {
            uint32_t Ah[2][4], Al[2][4];
            #pragma unroll
            for (int am = 0; am < 2; am++) {
                uint32_t ao = (uint32_t)(Moff * 80) + a_lo + ks * 32;
                ldm4(Ah[am], bb + (uint32_t)((am * 2) * GTA) + ao);
                ldm4(Al[am], bb + (uint32_t)((am * 2 + 1) * GTA) + ao);
            }
            #pragma unroll
            for (int g = 0; g < 6; g++) {
                uint32_t bhf[4], blf[4];
                uint32_t bo2 = (uint32_t)(Noff * 80) + b_lo + ks * 32;
                ldm4(bhf, bb + GB_B + (uint32_t)((2 * g) * GTB) + bo2);
                ldm4(blf, bb + GB_B + (uint32_t)((2 * g + 1) * GTB) + bo2);
                const int am = (g < 3) ? 0 : 1;
                #pragma unroll
                for (int nt = 0; nt < 2; nt++) {
                    const uint32_t* Bh = &bhf[nt * 2];
                    const uint32_t* Bl = &blf[nt * 2];
                    mma16816(acc[g][nt], Ah[am], Bh);
                    mma16816(acc[g][nt], Ah[am], Bl);
                    mma16816(acc[g][nt], Al[am], Bh);
                }
            }
        }
        __syncthreads();
    }

    #pragma unroll
    for (int rp = 0; rp < 2; rp++) {
        int row = m0 + Moff + row0 + rp * 8;
        #pragma unroll
        for (int nt = 0; nt < 2; nt++) {
            int cl = Noff + nt * 8 + qb * 2;
            int colG = f0 + cl;
            float o2[2];
            #pragma unroll
            for (int j = 0; j < 2; j++) {
                int ci = rp * 2 + j;
                float ir  = acc[0][nt][ci] + sbias[cl + j];
                float iz  = acc[1][nt][ci] + sbias[32 + cl + j];
                float in_ = acc[2][nt][ci] + sbias[64 + cl + j];
                float hr  = acc[3][nt][ci] + sbias[96 + cl + j];
                float hz  = acc[4][nt][ci] + sbias[128 + cl + j];
                float hn  = acc[5][nt][ci] + sbias[160 + cl + j];
                float r = sigmf(ir + hr), z = sigmf(iz + hz);
                float n = tanhf(in_ + r * hn);
                float h = g_af[row * FPD + colG + j];
                o2[j] = fmaxf((1.f - z) * n + z * h, 0.f);
            }
            *(float2*)&out[row * FPD + colG] = make_float2(o2[0], o2[1]);
        }
    }
}

// ---------------------------------------------------------------------------
// Launcher
// ---------------------------------------------------------------------------
extern "C" void kernel_launch(void* const* d_in, const int* in_sizes, int n_in,
                              void* d_out, int out_size)
{
    const float* atom_list = (const float*)d_in[0];
    const float* bond_list = (const float*)d_in[1];
    const int*   adeg      = (const int*)  d_in[2];
    const int*   bdeg      = (const int*)  d_in[3];
    const float* W_atom   = (const float*)d_in[5];
    const float* b_atom   = (const float*)d_in[6];
    const float* W_nbr    = (const float*)d_in[7];
    const float* b_nbr    = (const float*)d_in[8];
    const float* W_align  = (const float*)d_in[9];
    const float* b_align  = (const float*)d_in[10];
    const float* W_attend = (const float*)d_in[11];
    const float* b_attend = (const float*)d_in[12];
    const float* W_ih     = (const float*)d_in[13];
    const float* b_ih     = (const float*)d_in[14];
    const float* W_hh     = (const float*)d_in[15];
    const float* b_hh     = (const float*)d_in[16];
    float* out = (float*)d_out;
    (void)in_sizes; (void)n_in; (void)out_size;

    cudaFuncSetAttribute(proj_kernel, cudaFuncAttributeMaxDynamicSharedMemorySize, PJ_SMEM);
    cudaFuncSetAttribute(ctx_mma,     cudaFuncAttributeMaxDynamicSharedMemorySize, CTX_SMEM);
    cudaFuncSetAttribute(gru_mma,     cudaFuncAttributeMaxDynamicSharedMemorySize, GB_SMEM);

    prep_w<<<(3 * FPD * FPD + 255) / 256, 256>>>(W_attend, W_ih, W_hh);

    proj_kernel<<<NATOMS / PJ_ATOMS, 256, PJ_SMEM>>>(
        atom_list, bond_list, W_atom, b_atom, W_nbr);

    attn2_kernel<<<NATOMS / B_ATOMS, 256>>>(adeg, bdeg, b_nbr, W_align, b_align);

    dim3 gc(NATOMS / 128, FPD / 64);
    ctx_mma<<<gc, 256, CTX_SMEM>>>(b_attend);

    dim3 gg(NATOMS / 64, FPD / 32);
    gru_mma<<<gg, 256, GB_SMEM>>>(b_ih, b_hh, out);
}

// round 11
// speedup vs baseline: 1.4560x; 1.0001x over previous
#include <cuda_runtime.h>
#include <cuda_bf16.h>
#include <math.h>
#include <stdint.h>

// Problem constants
#define BQ   512
#define LQ   128
#define MQ   6
#define AD   39
#define BD   10
#define CD   49
#define FPD  256
#define NATOMS (BQ * LQ)   // 65536

// ---------------------------------------------------------------------------
// Device-global scratch (allocation-free rule)
// ---------------------------------------------------------------------------
__device__ __align__(16) float g_af[NATOMS * FPD];
__device__ __align__(16) float g_PA[NATOMS * FPD];   // atom part of nbr proj
__device__ __align__(16) float g_PB[NATOMS * FPD];   // bond part of nbr proj
__device__ __align__(16) float g_asum[NATOMS];
__device__ __align__(16) __nv_bfloat16 g_s_hi[NATOMS * FPD],  g_s_lo[NATOMS * FPD];
__device__ __align__(16) __nv_bfloat16 g_af_hi[NATOMS * FPD], g_af_lo[NATOMS * FPD];
__device__ __align__(16) __nv_bfloat16 g_cx_hi[NATOMS * FPD], g_cx_lo[NATOMS * FPD];
__device__ __align__(16) __nv_bfloat16 g_Wat_h[FPD * FPD],     g_Wat_l[FPD * FPD];
__device__ __align__(16) __nv_bfloat16 g_Wih_h[3 * FPD * FPD], g_Wih_l[3 * FPD * FPD];
__device__ __align__(16) __nv_bfloat16 g_Whh_h[3 * FPD * FPD], g_Whh_l[3 * FPD * FPD];

// ---------------------------------------------------------------------------
// Helpers
// ---------------------------------------------------------------------------
__device__ __forceinline__ uint32_t s2u(const void* p) {
    uint32_t a;
    asm("{ .reg .u64 t; cvta.to.shared.u64 t, %1; cvt.u32.u64 %0, t; }" : "=r"(a) : "l"(p));
    return a;
}
__device__ __forceinline__ void mma16816(float* c, const uint32_t* a, const uint32_t* b) {
    asm volatile("mma.sync.aligned.m16n8k16.row.col.f32.bf16.bf16.f32 "
        "{%0,%1,%2,%3}, {%4,%5,%6,%7}, {%8,%9}, {%0,%1,%2,%3};"
        : "+f"(c[0]), "+f"(c[1]), "+f"(c[2]), "+f"(c[3])
        : "r"(a[0]), "r"(a[1]), "r"(a[2]), "r"(a[3]), "r"(b[0]), "r"(b[1]));
}
__device__ __forceinline__ void ldm4(uint32_t* r, uint32_t addr) {
    asm volatile("ldmatrix.sync.aligned.m8n8.x4.shared.b16 {%0,%1,%2,%3}, [%4];"
        : "=r"(r[0]), "=r"(r[1]), "=r"(r[2]), "=r"(r[3]) : "r"(addr));
}
__device__ __forceinline__ void cpa16(uint32_t d, const void* s) {
    asm volatile("cp.async.cg.shared.global [%0], [%1], 16;" :: "r"(d), "l"(s) : "memory");
}
#define CP_COMMIT() asm volatile("cp.async.commit_group;" ::: "memory")
#define CP_WAIT0()  asm volatile("cp.async.wait_group 0;" ::: "memory")

__device__ __forceinline__ float leakyf(float x) { return x > 0.f ? x : 0.01f * x; }
__device__ __forceinline__ float sigmf(float x)  { return 1.f / (1.f + expf(-x)); }
__device__ __forceinline__ void split2(float v, __nv_bfloat16& h, __nv_bfloat16& l) {
    h = __float2bfloat16(v);
    l = __float2bfloat16(v - __bfloat162float(h));
}
__device__ __forceinline__ uint32_t pk2(__nv_bfloat16 a, __nv_bfloat16 b) {
    return (uint32_t)__bfloat16_as_ushort(a) | ((uint32_t)__bfloat16_as_ushort(b) << 16);
}

// ---------------------------------------------------------------------------
// Kernel 0: split weights to bf16 hi/lo pairs
// ---------------------------------------------------------------------------
__global__ void prep_w(const float* __restrict__ Wat, const float* __restrict__ Wih,
                       const float* __restrict__ Whh) {
    int i = blockIdx.x * 256 + threadIdx.x;
    if (i < FPD * FPD)     split2(Wat[i], g_Wat_h[i], g_Wat_l[i]);
    if (i < 3 * FPD * FPD) {
        split2(Wih[i], g_Wih_h[i], g_Wih_l[i]);
        split2(Whh[i], g_Whh_h[i], g_Whh_l[i]);
    }
}

// ---------------------------------------------------------------------------
// Kernel 1a: per-position projections (unchanged from R9 — passing)
// ---------------------------------------------------------------------------
#define PJ_ATOMS 64
#define PJ_WA  0
#define PJ_WNA (AD * FPD)
#define PJ_WNB (PJ_WNA + AD * FPD)
#define PJ_AR  (PJ_WNB + BD * FPD)
#define PJ_BR  (PJ_AR + 8 * 40)
#define PJ_SMEM ((PJ_BR + 8 * 12) * 4)

__global__ void __launch_bounds__(256, 2) proj_kernel(
    const float* __restrict__ atom_list, const float* __restrict__ bond_list,
    const float* __restrict__ W_atom,    const float* __restrict__ b_atom,
    const float* __restrict__ W_nbr)
{
    extern __shared__ float smem[];
    float* Wa   = smem + PJ_WA;
    float* WnA  = smem + PJ_WNA;
    float* WnB  = smem + PJ_WNB;
    float* arow = smem + PJ_AR;
    float* brow = smem + PJ_BR;

    const int tid = threadIdx.x;
    const int f   = tid;

    for (int i = tid; i < AD * FPD; i += 256) {
        int ff = i / AD, k = i % AD;
        Wa[k * FPD + ff]  = W_atom[ff * AD + k];
        WnA[k * FPD + ff] = W_nbr[ff * CD + k];
    }
    for (int i = tid; i < BD * FPD; i += 256) {
        int ff = i / BD, k = i % BD;
        WnB[k * FPD + ff] = W_nbr[ff * CD + AD + k];
    }
    const float ba = b_atom[f];
    __syncthreads();

    const int base = blockIdx.x * PJ_ATOMS;

    for (int ab = 0; ab < PJ_ATOMS; ab += 8) {
        const int atom0 = base + ab;
        __syncthreads();
        for (int i = tid; i < 8 * 49; i += 256) {
            int a = i / 49, j = i % 49;
            if (j < AD) arow[a * 40 + j] = atom_list[(atom0 + a) * AD + j];
            else        brow[a * 12 + (j - AD)] = bond_list[(atom0 + a) * BD + (j - AD)];
        }
        __syncthreads();

        float af8[8], pa8[8], pb8[8];
        #pragma unroll
        for (int a = 0; a < 8; a++) { af8[a] = ba; pa8[a] = 0.f; pb8[a] = 0.f; }

        #pragma unroll
        for (int k0 = 0; k0 < 36; k0 += 4) {
            float wa0 = Wa[(k0 + 0) * FPD + f], wa1 = Wa[(k0 + 1) * FPD + f];
            float wa2 = Wa[(k0 + 2) * FPD + f], wa3 = Wa[(k0 + 3) * FPD + f];
            float wn0 = WnA[(k0 + 0) * FPD + f], wn1 = WnA[(k0 + 1) * FPD + f];
            float wn2 = WnA[(k0 + 2) * FPD + f], wn3 = WnA[(k0 + 3) * FPD + f];
            #pragma unroll
            for (int a = 0; a < 8; a++) {
                float4 x = *(const float4*)&arow[a * 40 + k0];
                af8[a] += wa0 * x.x + wa1 * x.y + wa2 * x.z + wa3 * x.w;
                pa8[a] += wn0 * x.x + wn1 * x.y + wn2 * x.z + wn3 * x.w;
            }
        }
        {
            float wa0 = Wa[36 * FPD + f], wa1 = Wa[37 * FPD + f], wa2 = Wa[38 * FPD + f];
            float wn0 = WnA[36 * FPD + f], wn1 = WnA[37 * FPD + f], wn2 = WnA[38 * FPD + f];
            #pragma unroll
            for (int a = 0; a < 8; a++) {
                float x0 = arow[a * 40 + 36], x1 = arow[a * 40 + 37], x2 = arow[a * 40 + 38];
                af8[a] += wa0 * x0 + wa1 * x1 + wa2 * x2;
                pa8[a] += wn0 * x0 + wn1 * x1 + wn2 * x2;
            }
        }
        #pragma unroll
        for (int k0 = 0; k0 < 8; k0 += 4) {
            float wb0 = WnB[(k0 + 0) * FPD + f], wb1 = WnB[(k0 + 1) * FPD + f];
            float wb2 = WnB[(k0 + 2) * FPD + f], wb3 = WnB[(k0 + 3) * FPD + f];
            #pragma unroll
            for (int a = 0; a < 8; a++) {
                float4 x = *(const float4*)&brow[a * 12 + k0];
                pb8[a] += wb0 * x.x + wb1 * x.y + wb2 * x.z + wb3 * x.w;
            }
        }
        {
            float wb0 = WnB[8 * FPD + f], wb1 = WnB[9 * FPD + f];
            #pragma unroll
            for (int a = 0; a < 8; a++)
                pb8[a] += wb0 * brow[a * 12 + 8] + wb1 * brow[a * 12 + 9];
        }

        #pragma unroll
        for (int a = 0; a < 8; a++) {
            const int o = (atom0 + a) * FPD + f;
            float afv = leakyf(af8[a]);
            g_af[o] = afv;
            split2(afv, g_af_hi[o], g_af_lo[o]);
            g_PA[o] = pa8[a];
            g_PB[o] = pb8[a];
        }
    }
}

// ---------------------------------------------------------------------------
// Kernel 1b: attention — 4 atoms per iteration (fewer syncs, more MLP)
// ---------------------------------------------------------------------------
#define B_ATOMS 32

__global__ void __launch_bounds__(256) attn2_kernel(
    const int*   __restrict__ adeg,    const int*   __restrict__ bdeg,
    const float* __restrict__ b_nbr,   const float* __restrict__ W_align,
    const float* __restrict__ b_align)
{
    __shared__ float red[8 * 28];   // [8 warps][4 atoms * 7]
    __shared__ float padf[24];
    __shared__ int   idx[48];

    const int tid = threadIdx.x;
    const int f   = tid;
    const float bn   = b_nbr[f];
    const float bal  = b_align[0];
    const float wal1 = W_align[f];
    const float wal2 = W_align[FPD + f];

    const int warp = tid >> 5;
    const int lane = tid & 31;
    const int base = blockIdx.x * B_ATOMS;

    for (int ai = 0; ai < B_ATOMS; ai += 4) {
        const int atom0 = base + ai;
        const int bmol  = atom0 / LQ;

        __syncthreads();
        if (tid < 48) {
            int a = tid / 12, j = tid % 12;
            int atom = atom0 + a;
            if (j < MQ) {
                int ia = adeg[atom * MQ + j];
                idx[a * 12 + j] = ia;
                padf[a * 6 + j] = (ia == LQ - 1) ? 1.f : 0.f;
            } else {
                idx[a * 12 + j] = bdeg[atom * MQ + (j - MQ)];
            }
        }
        __syncthreads();

        float nfs[4][MQ];
        float v[28];
        #pragma unroll
        for (int a = 0; a < 4; a++) {
            const int atom = atom0 + a;
            float afv = g_af[atom * FPD + f];
            v[a * 7] = afv * wal1;
            #pragma unroll
            for (int m = 0; m < MQ; m++) {
                int ja = bmol * LQ + idx[a * 12 + m];
                int jb = bmol * LQ + idx[a * 12 + 6 + m];
                float t = leakyf(g_PA[ja * FPD + f] + g_PB[jb * FPD + f] + bn);
                nfs[a][m] = t;
                v[a * 7 + 1 + m] = t * wal2;
            }
        }
        #pragma unroll
        for (int off = 16; off > 0; off >>= 1)
            #pragma unroll
            for (int j = 0; j < 28; j++)
                v[j] += __shfl_down_sync(0xffffffffu, v[j], off);
        if (lane == 0)
            #pragma unroll
            for (int j = 0; j < 28; j++) red[warp * 28 + j] = v[j];
        __syncthreads();

        #pragma unroll
        for (int a = 0; a < 4; a++) {
            float sums[7];
            #pragma unroll
            for (int j = 0; j < 7; j++) {
                float s = 0.f;
                #pragma unroll
                for (int w = 0; w < 8; w++) s += red[w * 28 + a * 7 + j];
                sums[j] = s;
            }
            float sc[MQ], mx = -INFINITY;
            #pragma unroll
            for (int m = 0; m < MQ; m++) {
                float s = leakyf(sums[0] + sums[1 + m] + bal);
                if (padf[a * 6 + m] > 0.5f) s += -9e8f;
                sc[m] = s;
                mx = fmaxf(mx, s);
            }
            float e[MQ], se = 0.f;
            #pragma unroll
            for (int m = 0; m < MQ; m++) { e[m] = expf(sc[m] - mx); se += e[m]; }
            float inv = 1.f / se;
            float asum = 0.f, sf = 0.f;
            #pragma unroll
            for (int m = 0; m < MQ; m++) {
                float aw = e[m] * inv;
                if (padf[a * 6 + m] > 0.5f) aw = 0.f;
                asum += aw;
                sf   += aw * nfs[a][m];
            }
            const int atom = atom0 + a;
            const int o = atom * FPD + f;
            split2(sf, g_s_hi[o], g_s_lo[o]);
            if (tid == 0) g_asum[atom] = asum;
        }
    }
}

// ---------------------------------------------------------------------------
// Kernel 2a: ctx — single-sync pipeline: {wait0; sync; issue(c+1); compute(c)}
// ---------------------------------------------------------------------------
#define CTX_AH 0
#define CTX_AL 10240
#define CTX_BH 20480
#define CTX_BL 25600
#define CTX_BUF 30720
#define CTX_BATT (2 * CTX_BUF)
#define CTX_SMEM (CTX_BATT + 256)

__global__ void __launch_bounds__(256) ctx_mma(const float* __restrict__ batt_g)
{
    extern __shared__ char sm[];
    const uint32_t sb = s2u(sm);
    float* sbatt = (float*)(sm + CTX_BATT);
    const int tid = threadIdx.x, wid = tid >> 5, lane = tid & 31;
    const int m0 = blockIdx.x * 128, n0 = blockIdx.y * 64;
    const int Moff = (wid & 3) * 32, Noff = (wid >> 2) * 32;

    if (tid < 64) sbatt[tid] = batt_g[n0 + tid];

    const int r_ = tid >> 2, q_ = tid & 3;
    const uint32_t soff = (uint32_t)(r_ * 80 + q_ * 16);
    const int aoff0 = (m0 + r_) * FPD + q_ * 8;
    const int aoff1 = (m0 + 64 + r_) * FPD + q_ * 8;
    const int boff  = (n0 + r_) * FPD + q_ * 8;

    const uint32_t a_lo = (uint32_t)((lane & 15) * 80 + (lane >> 4) * 16);
    const uint32_t b_lo = (uint32_t)(((lane & 7) + ((lane >> 4) << 3)) * 80 + ((lane >> 3) & 1) * 16);

    const int row0 = lane >> 2, qb = lane & 3;
    float acc[2][4][4] = {};

    // prologue: stage chunk 0
    cpa16(sb + CTX_AH + soff,        g_s_hi + aoff0);
    cpa16(sb + CTX_AH + 5120 + soff, g_s_hi + aoff1);
    cpa16(sb + CTX_AL + soff,        g_s_lo + aoff0);
    cpa16(sb + CTX_AL + 5120 + soff, g_s_lo + aoff1);
    cpa16(sb + CTX_BH + soff, g_Wat_h + boff);
    cpa16(sb + CTX_BL + soff, g_Wat_l + boff);
    CP_COMMIT();

    for (int c = 0; c < 8; c++) {
        CP_WAIT0();            // drain own group for chunk c
        __syncthreads();       // all groups drained; all reads of chunk c-1 done
        if (c < 7) {
            const int k0 = (c + 1) * 32;
            const uint32_t bo = ((c + 1) & 1) * CTX_BUF;
            cpa16(sb + bo + CTX_AH + soff,        g_s_hi + aoff0 + k0);
            cpa16(sb + bo + CTX_AH + 5120 + soff, g_s_hi + aoff1 + k0);
            cpa16(sb + bo + CTX_AL + soff,        g_s_lo + aoff0 + k0);
            cpa16(sb + bo + CTX_AL + 5120 + soff, g_s_lo + aoff1 + k0);
            cpa16(sb + bo + CTX_BH + soff, g_Wat_h + boff + k0);
            cpa16(sb + bo + CTX_BL + soff, g_Wat_l + boff + k0);
            CP_COMMIT();
        }
        const uint32_t bb = sb + (c & 1) * CTX_BUF;
        #pragma unroll
        for (int ks = 0; ks < 2; ks++) {
            uint32_t ah[2][4], al[2][4];
            #pragma unroll
            for (int mt = 0; mt < 2; mt++) {
                uint32_t ao = (uint32_t)((Moff + mt * 16) * 80) + a_lo + ks * 32;
                ldm4(ah[mt], bb + CTX_AH + ao);
                ldm4(al[mt], bb + CTX_AL + ao);
            }
            uint32_t bh[2][4], bl[2][4];
            #pragma unroll
            for (int p = 0; p < 2; p++) {
                uint32_t bo2 = (uint32_t)((Noff + p * 16) * 80) + b_lo + ks * 32;
                ldm4(bh[p], bb + CTX_BH + bo2);
                ldm4(bl[p], bb + CTX_BL + bo2);
            }
            #pragma unroll
            for (int mt = 0; mt < 2; mt++)
                #pragma unroll
                for (int nt = 0; nt < 4; nt++) {
                    const uint32_t* Bh = &bh[nt >> 1][(nt & 1) * 2];
                    const uint32_t* Bl = &bl[nt >> 1][(nt & 1) * 2];
                    mma16816(acc[mt][nt], ah[mt], Bh);
                    mma16816(acc[mt][nt], ah[mt], Bl);
                    mma16816(acc[mt][nt], al[mt], Bh);
                }
        }
    }

    #pragma unroll
    for (int mt = 0; mt < 2; mt++) {
        int r0 = m0 + Moff + mt * 16 + row0;
        float as0 = g_asum[r0], as1 = g_asum[r0 + 8];
        #pragma unroll
        for (int nt = 0; nt < 4; nt++) {
            int cl = Noff + nt * 8 + qb * 2;
            int col = n0 + cl;
            float b0 = sbatt[cl], b1 = sbatt[cl + 1];
            float t00 = acc[mt][nt][0] + as0 * b0, t01 = acc[mt][nt][1] + as0 * b1;
            float t10 = acc[mt][nt][2] + as1 * b0, t11 = acc[mt][nt][3] + as1 * b1;
            t00 = t00 > 0.f ? t00 : expm1f(t00);
            t01 = t01 > 0.f ? t01 : expm1f(t01);
            t10 = t10 > 0.f ? t10 : expm1f(t10);
            t11 = t11 > 0.f ? t11 : expm1f(t11);
            __nv_bfloat16 h0, l0, h1, l1;
            split2(t00, h0, l0); split2(t01, h1, l1);
            *(uint32_t*)&g_cx_hi[r0 * FPD + col] = pk2(h0, h1);
            *(uint32_t*)&g_cx_lo[r0 * FPD + col] = pk2(l0, l1);
            split2(t10, h0, l0); split2(t11, h1, l1);
            *(uint32_t*)&g_cx_hi[(r0 + 8) * FPD + col] = pk2(h0, h1);
            *(uint32_t*)&g_cx_lo[(r0 + 8) * FPD + col] = pk2(l0, l1);
        }
    }
}

// ---------------------------------------------------------------------------
// Kernel 2b: GRU — single-sync pipeline, otherwise R8/R9 layout (2 CTAs/SM)
// ---------------------------------------------------------------------------
#define GTA     5120
#define GTB     2560
#define GB_B    (4 * GTA)
#define GB_BUF  (GB_B + 12 * GTB)
#define GB_BIAS (2 * GB_BUF)
#define GB_SMEM (GB_BIAS + 768 + 32)

__global__ void __launch_bounds__(256) gru_mma(
    const float* __restrict__ b_ih, const float* __restrict__ b_hh,
    float* __restrict__ out)
{
    extern __shared__ char sm[];
    const uint32_t sb = s2u(sm);
    float* sbias = (float*)(sm + GB_BIAS);
    const int tid = threadIdx.x, wid = tid >> 5, lane = tid & 31;
    const int m0 = blockIdx.x * 64, f0 = blockIdx.y * 32;
    const int Moff = (wid >> 1) * 16, Noff = (wid & 1) * 16;

    if (tid < 192) {
        int g = tid >> 5, fl = tid & 31;
        sbias[tid] = (g < 3) ? b_ih[g * FPD + f0 + fl] : b_hh[(g - 3) * FPD + f0 + fl];
    }

    const int rA = tid >> 2;
    const int half = tid >> 7;
    const int rB = (tid >> 2) & 31;
    const int sg = tid & 3;
    const uint32_t aoffS = (uint32_t)(rA * 80 + sg * 16);
    const uint32_t boffS = (uint32_t)(rB * 80 + sg * 16);
    const int aRow  = (m0 + rA) * FPD + sg * 8;
    const int bRow0 = (0 * FPD + f0 + rB) * FPD + sg * 8;
    const int bRow1 = (1 * FPD + f0 + rB) * FPD + sg * 8;
    const int bRow2 = (2 * FPD + f0 + rB) * FPD + sg * 8;

    const __nv_bfloat16* srcA[4] = { g_cx_hi, g_cx_lo, g_af_hi, g_af_lo };
    const __nv_bfloat16* srcB[6] = {
        half ? g_Wih_l : g_Wih_h, half ? g_Wih_l : g_Wih_h, half ? g_Wih_l : g_Wih_h,
        half ? g_Whh_l : g_Whh_h, half ? g_Whh_l : g_Whh_h, half ? g_Whh_l : g_Whh_h };
    const int bRow[6] = { bRow0, bRow1, bRow2, bRow0, bRow1, bRow2 };

    const uint32_t a_lo = (uint32_t)((lane & 15) * 80 + (lane >> 4) * 16);
    const uint32_t b_lo = (uint32_t)(((lane & 7) + ((lane >> 4) << 3)) * 80 + ((lane >> 3) & 1) * 16);

    const int row0 = lane >> 2, qb = lane & 3;
    float acc[6][2][4] = {};

    // prologue: stage chunk 0
    #pragma unroll
    for (int t = 0; t < 4; t++) cpa16(sb + (uint32_t)(t * GTA) + aoffS, srcA[t] + aRow);
    #pragma unroll
    for (int g = 0; g < 6; g++)
        cpa16(sb + GB_B + (uint32_t)((2 * g + half) * GTB) + boffS, srcB[g] + bRow[g]);
    CP_COMMIT();

    for (int c = 0; c < 8; c++) {
        CP_WAIT0();
        __syncthreads();
        if (c < 7) {
            const int k0 = (c + 1) * 32;
            const uint32_t bs = sb + ((c + 1) & 1) * GB_BUF;
            #pragma unroll
            for (int t = 0; t < 4; t++)
                cpa16(bs + (uint32_t)(t * GTA) + aoffS, srcA[t] + aRow + k0);
            #pragma unroll
            for (int g = 0; g < 6; g++)
                cpa16(bs + GB_B + (uint32_t)((2 * g + half) * GTB) + boffS, srcB[g] + bRow[g] + k0);
            CP_COMMIT();
        }
        const uint32_t bb = sb + (c & 1) * GB_BUF;
        #pragma unroll
        for (int ks = 0; ks < 2; ks++) {
            uint32_t Ah[2][4], Al[2][4];
            #pragma unroll
            for (int am = 0; am < 2; am++) {
                uint32_t ao = (uint32_t)(Moff * 80) + a_lo + ks * 32;
                ldm4(Ah[am], bb + (uint32_t)((am * 2) * GTA) + ao);
                ldm4(Al[am], bb + (uint32_t)((am * 2 + 1) * GTA) + ao);
            }
            #pragma unroll
            for (int g = 0; g < 6; g++) {
                uint32_t bhf[4], blf[4];
                uint32_t bo2 = (uint32_t)(Noff * 80) + b_lo + ks * 32;
                ldm4(bhf, bb + GB_B + (uint32_t)((2 * g) * GTB) + bo2);
                ldm4(blf, bb + GB_B + (uint32_t)((2 * g + 1) * GTB) + bo2);
                const int am = (g < 3) ? 0 : 1;
                #pragma unroll
                for (int nt = 0; nt < 2; nt++) {
                    const uint32_t* Bh = &bhf[nt * 2];
                    const uint32_t* Bl = &blf[nt * 2];
                    mma16816(acc[g][nt], Ah[am], Bh);
                    mma16816(acc[g][nt], Ah[am], Bl);
                    mma16816(acc[g][nt], Al[am], Bh);
                }
            }
        }
    }

    // fused GRU + ReLU epilogue
    #pragma unroll
    for (int rp = 0; rp < 2; rp++) {
        int row = m0 + Moff + row0 + rp * 8;
        #pragma unroll
        for (int nt = 0; nt < 2; nt++) {
            int cl = Noff + nt * 8 + qb * 2;
            int colG = f0 + cl;
            float o2[2];
            #pragma unroll
            for (int j = 0; j < 2; j++) {
                int ci = rp * 2 + j;
                float ir  = acc[0][nt][ci] + sbias[cl + j];
                float iz  = acc[1][nt][ci] + sbias[32 + cl + j];
                float in_ = acc[2][nt][ci] + sbias[64 + cl + j];
                float hr  = acc[3][nt][ci] + sbias[96 + cl + j];
                float hz  = acc[4][nt][ci] + sbias[128 + cl + j];
                float hn  = acc[5][nt][ci] + sbias[160 + cl + j];
                float r = sigmf(ir + hr), z = sigmf(iz + hz);
                float n = tanhf(in_ + r * hn);
                float h = g_af[row * FPD + colG + j];
                o2[j] = fmaxf((1.f - z) * n + z * h, 0.f);
            }
            *(float2*)&out[row * FPD + colG] = make_float2(o2[0], o2[1]);
        }
    }
}

// ---------------------------------------------------------------------------
// Launcher
// ---------------------------------------------------------------------------
extern "C" void kernel_launch(void* const* d_in, const int* in_sizes, int n_in,
                              void* d_out, int out_size)
{
    const float* atom_list = (const float*)d_in[0];
    const float* bond_list = (const float*)d_in[1];
    const int*   adeg      = (const int*)  d_in[2];
    const int*   bdeg      = (const int*)  d_in[3];
    const float* W_atom   = (const float*)d_in[5];
    const float* b_atom   = (const float*)d_in[6];
    const float* W_nbr    = (const float*)d_in[7];
    const float* b_nbr    = (const float*)d_in[8];
    const float* W_align  = (const float*)d_in[9];
    const float* b_align  = (const float*)d_in[10];
    const float* W_attend = (const float*)d_in[11];
    const float* b_attend = (const float*)d_in[12];
    const float* W_ih     = (const float*)d_in[13];
    const float* b_ih     = (const float*)d_in[14];
    const float* W_hh     = (const float*)d_in[15];
    const float* b_hh     = (const float*)d_in[16];
    float* out = (float*)d_out;
    (void)in_sizes; (void)n_in; (void)out_size;

    cudaFuncSetAttribute(proj_kernel, cudaFuncAttributeMaxDynamicSharedMemorySize, PJ_SMEM);
    cudaFuncSetAttribute(ctx_mma,     cudaFuncAttributeMaxDynamicSharedMemorySize, CTX_SMEM);
    cudaFuncSetAttribute(gru_mma,     cudaFuncAttributeMaxDynamicSharedMemorySize, GB_SMEM);

    prep_w<<<(3 * FPD * FPD + 255) / 256, 256>>>(W_attend, W_ih, W_hh);

    proj_kernel<<<NATOMS / PJ_ATOMS, 256, PJ_SMEM>>>(
        atom_list, bond_list, W_atom, b_atom, W_nbr);

    attn2_kernel<<<NATOMS / B_ATOMS, 256>>>(adeg, bdeg, b_nbr, W_align, b_align);

    dim3 gc(NATOMS / 128, FPD / 64);
    ctx_mma<<<gc, 256, CTX_SMEM>>>(b_attend);

    dim3 gg(NATOMS / 64, FPD / 32);
    gru_mma<<<gg, 256, GB_SMEM>>>(b_ih, b_hh, out);
}

// round 12
// speedup vs baseline: 1.8570x; 1.2754x over previous
#include <cuda_runtime.h>
#include <cuda_fp16.h>
#include <math.h>
#include <stdint.h>

// Problem constants
#define BQ   512
#define LQ   128
#define MQ   6
#define AD   39
#define BD   10
#define CD   49
#define FPD  256
#define NATOMS (BQ * LQ)   // 65536

// ---------------------------------------------------------------------------
// Device-global scratch (allocation-free rule)
// fp16 2-pass scheme: activations split hi+lo (fp16), weights hi-only (fp16).
// ---------------------------------------------------------------------------
__device__ __align__(16) float g_af[NATOMS * FPD];
__device__ __align__(16) float g_PA[NATOMS * FPD];
__device__ __align__(16) float g_PB[NATOMS * FPD];
__device__ __align__(16) float g_asum[NATOMS];
__device__ __align__(16) __half g_s_hi[NATOMS * FPD],  g_s_lo[NATOMS * FPD];
__device__ __align__(16) __half g_af_hi[NATOMS * FPD], g_af_lo[NATOMS * FPD];
__device__ __align__(16) __half g_cx_hi[NATOMS * FPD], g_cx_lo[NATOMS * FPD];
__device__ __align__(16) __half g_Wat_h[FPD * FPD];
__device__ __align__(16) __half g_Wih_h[3 * FPD * FPD];
__device__ __align__(16) __half g_Whh_h[3 * FPD * FPD];

// ---------------------------------------------------------------------------
// Helpers
// ---------------------------------------------------------------------------
__device__ __forceinline__ uint32_t s2u(const void* p) {
    uint32_t a;
    asm("{ .reg .u64 t; cvta.to.shared.u64 t, %1; cvt.u32.u64 %0, t; }" : "=r"(a) : "l"(p));
    return a;
}
// fp16 m16n8k16, fp32 accumulate
__device__ __forceinline__ void mma16816(float* c, const uint32_t* a, const uint32_t* b) {
    asm volatile("mma.sync.aligned.m16n8k16.row.col.f32.f16.f16.f32 "
        "{%0,%1,%2,%3}, {%4,%5,%6,%7}, {%8,%9}, {%0,%1,%2,%3};"
        : "+f"(c[0]), "+f"(c[1]), "+f"(c[2]), "+f"(c[3])
        : "r"(a[0]), "r"(a[1]), "r"(a[2]), "r"(a[3]), "r"(b[0]), "r"(b[1]));
}
__device__ __forceinline__ void ldm4(uint32_t* r, uint32_t addr) {
    asm volatile("ldmatrix.sync.aligned.m8n8.x4.shared.b16 {%0,%1,%2,%3}, [%4];"
        : "=r"(r[0]), "=r"(r[1]), "=r"(r[2]), "=r"(r[3]) : "r"(addr));
}
__device__ __forceinline__ void cpa16(uint32_t d, const void* s) {
    asm volatile("cp.async.cg.shared.global [%0], [%1], 16;" :: "r"(d), "l"(s) : "memory");
}
#define CP_COMMIT() asm volatile("cp.async.commit_group;" ::: "memory")
#define CP_WAIT0()  asm volatile("cp.async.wait_group 0;" ::: "memory")

__device__ __forceinline__ float leakyf(float x) { return x > 0.f ? x : 0.01f * x; }
__device__ __forceinline__ float sigmf(float x)  { return 1.f / (1.f + expf(-x)); }
__device__ __forceinline__ void split2h(float v, __half& h, __half& l) {
    h = __float2half_rn(v);
    l = __float2half_rn(v - __half2float(h));
}
__device__ __forceinline__ uint32_t pk2h(__half a, __half b) {
    return (uint32_t)__half_as_ushort(a) | ((uint32_t)__half_as_ushort(b) << 16);
}

// ---------------------------------------------------------------------------
// Kernel 0: weights -> fp16 (hi only; lo not needed in 2-pass scheme)
// ---------------------------------------------------------------------------
__global__ void prep_w(const float* __restrict__ Wat, const float* __restrict__ Wih,
                       const float* __restrict__ Whh) {
    int i = blockIdx.x * 256 + threadIdx.x;
    if (i < FPD * FPD)     g_Wat_h[i] = __float2half_rn(Wat[i]);
    if (i < 3 * FPD * FPD) {
        g_Wih_h[i] = __float2half_rn(Wih[i]);
        g_Whh_h[i] = __float2half_rn(Whh[i]);
    }
}

// ---------------------------------------------------------------------------
// Kernel 1a: per-position projections (structure unchanged from R9/R11)
// ---------------------------------------------------------------------------
#define PJ_ATOMS 64
#define PJ_WA  0
#define PJ_WNA (AD * FPD)
#define PJ_WNB (PJ_WNA + AD * FPD)
#define PJ_AR  (PJ_WNB + BD * FPD)
#define PJ_BR  (PJ_AR + 8 * 40)
#define PJ_SMEM ((PJ_BR + 8 * 12) * 4)

__global__ void __launch_bounds__(256, 2) proj_kernel(
    const float* __restrict__ atom_list, const float* __restrict__ bond_list,
    const float* __restrict__ W_atom,    const float* __restrict__ b_atom,
    const float* __restrict__ W_nbr)
{
    extern __shared__ float smem[];
    float* Wa   = smem + PJ_WA;
    float* WnA  = smem + PJ_WNA;
    float* WnB  = smem + PJ_WNB;
    float* arow = smem + PJ_AR;
    float* brow = smem + PJ_BR;

    const int tid = threadIdx.x;
    const int f   = tid;

    for (int i = tid; i < AD * FPD; i += 256) {
        int ff = i / AD, k = i % AD;
        Wa[k * FPD + ff]  = W_atom[ff * AD + k];
        WnA[k * FPD + ff] = W_nbr[ff * CD + k];
    }
    for (int i = tid; i < BD * FPD; i += 256) {
        int ff = i / BD, k = i % BD;
        WnB[k * FPD + ff] = W_nbr[ff * CD + AD + k];
    }
    const float ba = b_atom[f];
    __syncthreads();

    const int base = blockIdx.x * PJ_ATOMS;

    for (int ab = 0; ab < PJ_ATOMS; ab += 8) {
        const int atom0 = base + ab;
        __syncthreads();
        for (int i = tid; i < 8 * 49; i += 256) {
            int a = i / 49, j = i % 49;
            if (j < AD) arow[a * 40 + j] = atom_list[(atom0 + a) * AD + j];
            else        brow[a * 12 + (j - AD)] = bond_list[(atom0 + a) * BD + (j - AD)];
        }
        __syncthreads();

        float af8[8], pa8[8], pb8[8];
        #pragma unroll
        for (int a = 0; a < 8; a++) { af8[a] = ba; pa8[a] = 0.f; pb8[a] = 0.f; }

        #pragma unroll
        for (int k0 = 0; k0 < 36; k0 += 4) {
            float wa0 = Wa[(k0 + 0) * FPD + f], wa1 = Wa[(k0 + 1) * FPD + f];
            float wa2 = Wa[(k0 + 2) * FPD + f], wa3 = Wa[(k0 + 3) * FPD + f];
            float wn0 = WnA[(k0 + 0) * FPD + f], wn1 = WnA[(k0 + 1) * FPD + f];
            float wn2 = WnA[(k0 + 2) * FPD + f], wn3 = WnA[(k0 + 3) * FPD + f];
            #pragma unroll
            for (int a = 0; a < 8; a++) {
                float4 x = *(const float4*)&arow[a * 40 + k0];
                af8[a] += wa0 * x.x + wa1 * x.y + wa2 * x.z + wa3 * x.w;
                pa8[a] += wn0 * x.x + wn1 * x.y + wn2 * x.z + wn3 * x.w;
            }
        }
        {
            float wa0 = Wa[36 * FPD + f], wa1 = Wa[37 * FPD + f], wa2 = Wa[38 * FPD + f];
            float wn0 = WnA[36 * FPD + f], wn1 = WnA[37 * FPD + f], wn2 = WnA[38 * FPD + f];
            #pragma unroll
            for (int a = 0; a < 8; a++) {
                float x0 = arow[a * 40 + 36], x1 = arow[a * 40 + 37], x2 = arow[a * 40 + 38];
                af8[a] += wa0 * x0 + wa1 * x1 + wa2 * x2;
                pa8[a] += wn0 * x0 + wn1 * x1 + wn2 * x2;
            }
        }
        #pragma unroll
        for (int k0 = 0; k0 < 8; k0 += 4) {
            float wb0 = WnB[(k0 + 0) * FPD + f], wb1 = WnB[(k0 + 1) * FPD + f];
            float wb2 = WnB[(k0 + 2) * FPD + f], wb3 = WnB[(k0 + 3) * FPD + f];
            #pragma unroll
            for (int a = 0; a < 8; a++) {
                float4 x = *(const float4*)&brow[a * 12 + k0];
                pb8[a] += wb0 * x.x + wb1 * x.y + wb2 * x.z + wb3 * x.w;
            }
        }
        {
            float wb0 = WnB[8 * FPD + f], wb1 = WnB[9 * FPD + f];
            #pragma unroll
            for (int a = 0; a < 8; a++)
                pb8[a] += wb0 * brow[a * 12 + 8] + wb1 * brow[a * 12 + 9];
        }

        #pragma unroll
        for (int a = 0; a < 8; a++) {
            const int o = (atom0 + a) * FPD + f;
            float afv = leakyf(af8[a]);
            g_af[o] = afv;
            split2h(afv, g_af_hi[o], g_af_lo[o]);
            g_PA[o] = pa8[a];
            g_PB[o] = pb8[a];
        }
    }
}

// ---------------------------------------------------------------------------
// Kernel 1b: attention (unchanged logic; stores fp16 splits of s)
// ---------------------------------------------------------------------------
#define B_ATOMS 32

__global__ void __launch_bounds__(256) attn2_kernel(
    const int*   __restrict__ adeg,    const int*   __restrict__ bdeg,
    const float* __restrict__ b_nbr,   const float* __restrict__ W_align,
    const float* __restrict__ b_align)
{
    __shared__ float red[8 * 28];
    __shared__ float padf[24];
    __shared__ int   idx[48];

    const int tid = threadIdx.x;
    const int f   = tid;
    const float bn   = b_nbr[f];
    const float bal  = b_align[0];
    const float wal1 = W_align[f];
    const float wal2 = W_align[FPD + f];

    const int warp = tid >> 5;
    const int lane = tid & 31;
    const int base = blockIdx.x * B_ATOMS;

    for (int ai = 0; ai < B_ATOMS; ai += 4) {
        const int atom0 = base + ai;
        const int bmol  = atom0 / LQ;

        __syncthreads();
        if (tid < 48) {
            int a = tid / 12, j = tid % 12;
            int atom = atom0 + a;
            if (j < MQ) {
                int ia = adeg[atom * MQ + j];
                idx[a * 12 + j] = ia;
                padf[a * 6 + j] = (ia == LQ - 1) ? 1.f : 0.f;
            } else {
                idx[a * 12 + j] = bdeg[atom * MQ + (j - MQ)];
            }
        }
        __syncthreads();

        float nfs[4][MQ];
        float v[28];
        #pragma unroll
        for (int a = 0; a < 4; a++) {
            const int atom = atom0 + a;
            float afv = g_af[atom * FPD + f];
            v[a * 7] = afv * wal1;
            #pragma unroll
            for (int m = 0; m < MQ; m++) {
                int ja = bmol * LQ + idx[a * 12 + m];
                int jb = bmol * LQ + idx[a * 12 + 6 + m];
                float t = leakyf(g_PA[ja * FPD + f] + g_PB[jb * FPD + f] + bn);
                nfs[a][m] = t;
                v[a * 7 + 1 + m] = t * wal2;
            }
        }
        #pragma unroll
        for (int off = 16; off > 0; off >>= 1)
            #pragma unroll
            for (int j = 0; j < 28; j++)
                v[j] += __shfl_down_sync(0xffffffffu, v[j], off);
        if (lane == 0)
            #pragma unroll
            for (int j = 0; j < 28; j++) red[warp * 28 + j] = v[j];
        __syncthreads();

        #pragma unroll
        for (int a = 0; a < 4; a++) {
            float sums[7];
            #pragma unroll
            for (int j = 0; j < 7; j++) {
                float s = 0.f;
                #pragma unroll
                for (int w = 0; w < 8; w++) s += red[w * 28 + a * 7 + j];
                sums[j] = s;
            }
            float sc[MQ], mx = -INFINITY;
            #pragma unroll
            for (int m = 0; m < MQ; m++) {
                float s = leakyf(sums[0] + sums[1 + m] + bal);
                if (padf[a * 6 + m] > 0.5f) s += -9e8f;
                sc[m] = s;
                mx = fmaxf(mx, s);
            }
            float e[MQ], se = 0.f;
            #pragma unroll
            for (int m = 0; m < MQ; m++) { e[m] = expf(sc[m] - mx); se += e[m]; }
            float inv = 1.f / se;
            float asum = 0.f, sf = 0.f;
            #pragma unroll
            for (int m = 0; m < MQ; m++) {
                float aw = e[m] * inv;
                if (padf[a * 6 + m] > 0.5f) aw = 0.f;
                asum += aw;
                sf   += aw * nfs[a][m];
            }
            const int atom = atom0 + a;
            const int o = atom * FPD + f;
            split2h(sf, g_s_hi[o], g_s_lo[o]);
            if (tid == 0) g_asum[atom] = asum;
        }
    }
}

// ---------------------------------------------------------------------------
// Kernel 2a: ctx — fp16 2-pass (sh*Wh + sl*Wh), B-lo gone.
// ---------------------------------------------------------------------------
#define CTX_AH 0
#define CTX_AL 10240
#define CTX_BH 20480
#define CTX_BUF 25600
#define CTX_BATT (2 * CTX_BUF)
#define CTX_SMEM (CTX_BATT + 256)

__global__ void __launch_bounds__(256) ctx_mma(const float* __restrict__ batt_g)
{
    extern __shared__ char sm[];
    const uint32_t sb = s2u(sm);
    float* sbatt = (float*)(sm + CTX_BATT);
    const int tid = threadIdx.x, wid = tid >> 5, lane = tid & 31;
    const int m0 = blockIdx.x * 128, n0 = blockIdx.y * 64;
    const int Moff = (wid & 3) * 32, Noff = (wid >> 2) * 32;

    if (tid < 64) sbatt[tid] = batt_g[n0 + tid];

    const int r_ = tid >> 2, q_ = tid & 3;
    const uint32_t soff = (uint32_t)(r_ * 80 + q_ * 16);
    const int aoff0 = (m0 + r_) * FPD + q_ * 8;
    const int aoff1 = (m0 + 64 + r_) * FPD + q_ * 8;
    const int boff  = (n0 + r_) * FPD + q_ * 8;

    const uint32_t a_lo = (uint32_t)((lane & 15) * 80 + (lane >> 4) * 16);
    const uint32_t b_lo = (uint32_t)(((lane & 7) + ((lane >> 4) << 3)) * 80 + ((lane >> 3) & 1) * 16);

    const int row0 = lane >> 2, qb = lane & 3;
    float acc[2][4][4] = {};

    // prologue: stage chunk 0
    cpa16(sb + CTX_AH + soff,        g_s_hi + aoff0);
    cpa16(sb + CTX_AH + 5120 + soff, g_s_hi + aoff1);
    cpa16(sb + CTX_AL + soff,        g_s_lo + aoff0);
    cpa16(sb + CTX_AL + 5120 + soff, g_s_lo + aoff1);
    cpa16(sb + CTX_BH + soff, g_Wat_h + boff);
    CP_COMMIT();

    for (int c = 0; c < 8; c++) {
        CP_WAIT0();
        __syncthreads();
        if (c < 7) {
            const int k0 = (c + 1) * 32;
            const uint32_t bo = ((c + 1) & 1) * CTX_BUF;
            cpa16(sb + bo + CTX_AH + soff,        g_s_hi + aoff0 + k0);
            cpa16(sb + bo + CTX_AH + 5120 + soff, g_s_hi + aoff1 + k0);
            cpa16(sb + bo + CTX_AL + soff,        g_s_lo + aoff0 + k0);
            cpa16(sb + bo + CTX_AL + 5120 + soff, g_s_lo + aoff1 + k0);
            cpa16(sb + bo + CTX_BH + soff, g_Wat_h + boff + k0);
            CP_COMMIT();
        }
        const uint32_t bb = sb + (c & 1) * CTX_BUF;
        #pragma unroll
        for (int ks = 0; ks < 2; ks++) {
            uint32_t ah[2][4], al[2][4];
            #pragma unroll
            for (int mt = 0; mt < 2; mt++) {
                uint32_t ao = (uint32_t)((Moff + mt * 16) * 80) + a_lo + ks * 32;
                ldm4(ah[mt], bb + CTX_AH + ao);
                ldm4(al[mt], bb + CTX_AL + ao);
            }
            uint32_t bh[2][4];
            #pragma unroll
            for (int p = 0; p < 2; p++) {
                uint32_t bo2 = (uint32_t)((Noff + p * 16) * 80) + b_lo + ks * 32;
                ldm4(bh[p], bb + CTX_BH + bo2);
            }
            #pragma unroll
            for (int mt = 0; mt < 2; mt++)
                #pragma unroll
                for (int nt = 0; nt < 4; nt++) {
                    const uint32_t* Bh = &bh[nt >> 1][(nt & 1) * 2];
                    mma16816(acc[mt][nt], ah[mt], Bh);
                    mma16816(acc[mt][nt], al[mt], Bh);
                }
        }
    }

    #pragma unroll
    for (int mt = 0; mt < 2; mt++) {
        int r0 = m0 + Moff + mt * 16 + row0;
        float as0 = g_asum[r0], as1 = g_asum[r0 + 8];
        #pragma unroll
        for (int nt = 0; nt < 4; nt++) {
            int cl = Noff + nt * 8 + qb * 2;
            int col = n0 + cl;
            float b0 = sbatt[cl], b1 = sbatt[cl + 1];
            float t00 = acc[mt][nt][0] + as0 * b0, t01 = acc[mt][nt][1] + as0 * b1;
            float t10 = acc[mt][nt][2] + as1 * b0, t11 = acc[mt][nt][3] + as1 * b1;
            t00 = t00 > 0.f ? t00 : expm1f(t00);
            t01 = t01 > 0.f ? t01 : expm1f(t01);
            t10 = t10 > 0.f ? t10 : expm1f(t10);
            t11 = t11 > 0.f ? t11 : expm1f(t11);
            __half h0, l0, h1, l1;
            split2h(t00, h0, l0); split2h(t01, h1, l1);
            *(uint32_t*)&g_cx_hi[r0 * FPD + col] = pk2h(h0, h1);
            *(uint32_t*)&g_cx_lo[r0 * FPD + col] = pk2h(l0, l1);
            split2h(t10, h0, l0); split2h(t11, h1, l1);
            *(uint32_t*)&g_cx_hi[(r0 + 8) * FPD + col] = pk2h(h0, h1);
            *(uint32_t*)&g_cx_lo[(r0 + 8) * FPD + col] = pk2h(l0, l1);
        }
    }
}

// ---------------------------------------------------------------------------
// Kernel 2b: GRU — fp16 2-pass; B hi-only (6 tiles); smem 72.5KB -> 3 CTAs/SM.
// ---------------------------------------------------------------------------
#define GTA     5120                 // 64 x 80
#define GTB     2560                 // 32 x 80
#define GB_B    (4 * GTA)            // 20480
#define GB_BUF  (GB_B + 6 * GTB)     // 35840
#define GB_BIAS (2 * GB_BUF)         // 71680: float[192]
#define GB_SMEM (GB_BIAS + 768 + 32)

__global__ void __launch_bounds__(256, 3) gru_mma(
    const float* __restrict__ b_ih, const float* __restrict__ b_hh,
    float* __restrict__ out)
{
    extern __shared__ char sm[];
    const uint32_t sb = s2u(sm);
    float* sbias = (float*)(sm + GB_BIAS);
    const int tid = threadIdx.x, wid = tid >> 5, lane = tid & 31;
    const int m0 = blockIdx.x * 64, f0 = blockIdx.y * 32;
    const int Moff = (wid >> 1) * 16, Noff = (wid & 1) * 16;

    if (tid < 192) {
        int g = tid >> 5, fl = tid & 31;
        sbias[tid] = (g < 3) ? b_ih[g * FPD + f0 + fl] : b_hh[(g - 3) * FPD + f0 + fl];
    }

    // staging maps: A tiles by (rA, sg); B tiles: half-group loads 3 gates.
    const int rA = tid >> 2;             // 0..63
    const int half = tid >> 7;           // gate group: 0 -> gates 0..2, 1 -> 3..5
    const int rB = (tid >> 2) & 31;      // 0..31
    const int sg = tid & 3;
    const uint32_t aoffS = (uint32_t)(rA * 80 + sg * 16);
    const uint32_t boffS = (uint32_t)(rB * 80 + sg * 16);
    const int aRow  = (m0 + rA) * FPD + sg * 8;
    const int bRow0 = (0 * FPD + f0 + rB) * FPD + sg * 8;
    const int bRow1 = (1 * FPD + f0 + rB) * FPD + sg * 8;
    const int bRow2 = (2 * FPD + f0 + rB) * FPD + sg * 8;

    const __half* srcA[4] = { g_cx_hi, g_cx_lo, g_af_hi, g_af_lo };
    const __half* wsrc = half ? g_Whh_h : g_Wih_h;     // this thread's gate family
    const int bRow[3] = { bRow0, bRow1, bRow2 };
    const int gBase = half * 3;

    const uint32_t a_lo = (uint32_t)((lane & 15) * 80 + (lane >> 4) * 16);
    const uint32_t b_lo = (uint32_t)(((lane & 7) + ((lane >> 4) << 3)) * 80 + ((lane >> 3) & 1) * 16);

    const int row0 = lane >> 2, qb = lane & 3;
    float acc[6][2][4] = {};

    // prologue: stage chunk 0
    #pragma unroll
    for (int t = 0; t < 4; t++) cpa16(sb + (uint32_t)(t * GTA) + aoffS, srcA[t] + aRow);
    #pragma unroll
    for (int j = 0; j < 3; j++)
        cpa16(sb + GB_B + (uint32_t)((gBase + j) * GTB) + boffS, wsrc + bRow[j]);
    CP_COMMIT();

    for (int c = 0; c < 8; c++) {
        CP_WAIT0();
        __syncthreads();
        if (c < 7) {
            const int k0 = (c + 1) * 32;
            const uint32_t bs = sb + ((c + 1) & 1) * GB_BUF;
            #pragma unroll
            for (int t = 0; t < 4; t++)
                cpa16(bs + (uint32_t)(t * GTA) + aoffS, srcA[t] + aRow + k0);
            #pragma unroll
            for (int j = 0; j < 3; j++)
                cpa16(bs + GB_B + (uint32_t)((gBase + j) * GTB) + boffS, wsrc + bRow[j] + k0);
            CP_COMMIT();
        }
        const uint32_t bb = sb + (c & 1) * GB_BUF;
        #pragma unroll
        for (int ks = 0; ks < 2; ks++) {
            uint32_t Ah[2][4], Al[2][4];   // [am: 0=ctx 1=af]
            #pragma unroll
            for (int am = 0; am < 2; am++) {
                uint32_t ao = (uint32_t)(Moff * 80) + a_lo + ks * 32;
                ldm4(Ah[am], bb + (uint32_t)((am * 2) * GTA) + ao);
                ldm4(Al[am], bb + (uint32_t)((am * 2 + 1) * GTA) + ao);
            }
            #pragma unroll
            for (int g = 0; g < 6; g++) {
                uint32_t bhf[4];
                uint32_t bo2 = (uint32_t)(Noff * 80) + b_lo + ks * 32;
                ldm4(bhf, bb + GB_B + (uint32_t)(g * GTB) + bo2);
                const int am = (g < 3) ? 0 : 1;
                #pragma unroll
                for (int nt = 0; nt < 2; nt++) {
                    const uint32_t* Bh = &bhf[nt * 2];
                    mma16816(acc[g][nt], Ah[am], Bh);
                    mma16816(acc[g][nt], Al[am], Bh);
                }
            }
        }
    }

    // fused GRU + ReLU epilogue
    #pragma unroll
    for (int rp = 0; rp < 2; rp++) {
        int row = m0 + Moff + row0 + rp * 8;
        #pragma unroll
        for (int nt = 0; nt < 2; nt++) {
            int cl = Noff + nt * 8 + qb * 2;
            int colG = f0 + cl;
            float o2[2];
            #pragma unroll
            for (int j = 0; j < 2; j++) {
                int ci = rp * 2 + j;
                float ir  = acc[0][nt][ci] + sbias[cl + j];
                float iz  = acc[1][nt][ci] + sbias[32 + cl + j];
                float in_ = acc[2][nt][ci] + sbias[64 + cl + j];
                float hr  = acc[3][nt][ci] + sbias[96 + cl + j];
                float hz  = acc[4][nt][ci] + sbias[128 + cl + j];
                float hn  = acc[5][nt][ci] + sbias[160 + cl + j];
                float r = sigmf(ir + hr), z = sigmf(iz + hz);
                float n = tanhf(in_ + r * hn);
                float h = g_af[row * FPD + colG + j];
                o2[j] = fmaxf((1.f - z) * n + z * h, 0.f);
            }
            *(float2*)&out[row * FPD + colG] = make_float2(o2[0], o2[1]);
        }
    }
}

// ---------------------------------------------------------------------------
// Launcher
// ---------------------------------------------------------------------------
extern "C" void kernel_launch(void* const* d_in, const int* in_sizes, int n_in,
                              void* d_out, int out_size)
{
    const float* atom_list = (const float*)d_in[0];
    const float* bond_list = (const float*)d_in[1];
    const int*   adeg      = (const int*)  d_in[2];
    const int*   bdeg      = (const int*)  d_in[3];
    const float* W_atom   = (const float*)d_in[5];
    const float* b_atom   = (const float*)d_in[6];
    const float* W_nbr    = (const float*)d_in[7];
    const float* b_nbr    = (const float*)d_in[8];
    const float* W_align  = (const float*)d_in[9];
    const float* b_align  = (const float*)d_in[10];
    const float* W_attend = (const float*)d_in[11];
    const float* b_attend = (const float*)d_in[12];
    const float* W_ih     = (const float*)d_in[13];
    const float* b_ih     = (const float*)d_in[14];
    const float* W_hh     = (const float*)d_in[15];
    const float* b_hh     = (const float*)d_in[16];
    float* out = (float*)d_out;
    (void)in_sizes; (void)n_in; (void)out_size;

    cudaFuncSetAttribute(proj_kernel, cudaFuncAttributeMaxDynamicSharedMemorySize, PJ_SMEM);
    cudaFuncSetAttribute(ctx_mma,     cudaFuncAttributeMaxDynamicSharedMemorySize, CTX_SMEM);
    cudaFuncSetAttribute(gru_mma,     cudaFuncAttributeMaxDynamicSharedMemorySize, GB_SMEM);

    prep_w<<<(3 * FPD * FPD + 255) / 256, 256>>>(W_attend, W_ih, W_hh);

    proj_kernel<<<NATOMS / PJ_ATOMS, 256, PJ_SMEM>>>(
        atom_list, bond_list, W_atom, b_atom, W_nbr);

    attn2_kernel<<<NATOMS / B_ATOMS, 256>>>(adeg, bdeg, b_nbr, W_align, b_align);

    dim3 gc(NATOMS / 128, FPD / 64);
    ctx_mma<<<gc, 256, CTX_SMEM>>>(b_attend);

    dim3 gg(NATOMS / 64, FPD / 32);
    gru_mma<<<gg, 256, GB_SMEM>>>(b_ih, b_hh, out);
}

// round 13
// speedup vs baseline: 2.2366x; 1.2044x over previous
#include <cuda_runtime.h>
#include <cuda_fp16.h>
#include <math.h>
#include <stdint.h>

// Problem constants
#define BQ   512
#define LQ   128
#define MQ   6
#define AD   39
#define BD   10
#define CD   49
#define FPD  256
#define NATOMS (BQ * LQ)   // 65536

// ---------------------------------------------------------------------------
// Device-global scratch (allocation-free rule)
// ---------------------------------------------------------------------------
__device__ __align__(16) float g_af[NATOMS * FPD];
__device__ __align__(16) float g_PA[NATOMS * FPD];
__device__ __align__(16) float g_PB[NATOMS * FPD];
__device__ __align__(16) float g_asum[NATOMS];
__device__ __align__(16) __half g_s_hi[NATOMS * FPD],  g_s_lo[NATOMS * FPD];
__device__ __align__(16) __half g_af_hi[NATOMS * FPD], g_af_lo[NATOMS * FPD];
__device__ __align__(16) __half g_cx_hi[NATOMS * FPD], g_cx_lo[NATOMS * FPD];
__device__ __align__(16) __half g_Wat_h[FPD * FPD];
__device__ __align__(16) __half g_Wih_h[3 * FPD * FPD];
__device__ __align__(16) __half g_Whh_h[3 * FPD * FPD];

// ---------------------------------------------------------------------------
// Helpers
// ---------------------------------------------------------------------------
__device__ __forceinline__ uint32_t s2u(const void* p) {
    uint32_t a;
    asm("{ .reg .u64 t; cvta.to.shared.u64 t, %1; cvt.u32.u64 %0, t; }" : "=r"(a) : "l"(p));
    return a;
}
__device__ __forceinline__ void mma16816(float* c, const uint32_t* a, const uint32_t* b) {
    asm volatile("mma.sync.aligned.m16n8k16.row.col.f32.f16.f16.f32 "
        "{%0,%1,%2,%3}, {%4,%5,%6,%7}, {%8,%9}, {%0,%1,%2,%3};"
        : "+f"(c[0]), "+f"(c[1]), "+f"(c[2]), "+f"(c[3])
        : "r"(a[0]), "r"(a[1]), "r"(a[2]), "r"(a[3]), "r"(b[0]), "r"(b[1]));
}
__device__ __forceinline__ void ldm4(uint32_t* r, uint32_t addr) {
    asm volatile("ldmatrix.sync.aligned.m8n8.x4.shared.b16 {%0,%1,%2,%3}, [%4];"
        : "=r"(r[0]), "=r"(r[1]), "=r"(r[2]), "=r"(r[3]) : "r"(addr));
}
__device__ __forceinline__ void cpa16(uint32_t d, const void* s) {
    asm volatile("cp.async.cg.shared.global [%0], [%1], 16;" :: "r"(d), "l"(s) : "memory");
}
#define CP_COMMIT() asm volatile("cp.async.commit_group;" ::: "memory")
#define CP_WAIT0()  asm volatile("cp.async.wait_group 0;" ::: "memory")

__device__ __forceinline__ float leakyf(float x) { return x > 0.f ? x : 0.01f * x; }
__device__ __forceinline__ float sigmf(float x)  { return 1.f / (1.f + expf(-x)); }
__device__ __forceinline__ void split2h(float v, __half& h, __half& l) {
    h = __float2half_rn(v);
    l = __float2half_rn(v - __half2float(h));
}
__device__ __forceinline__ uint32_t pk2h(__half a, __half b) {
    return (uint32_t)__half_as_ushort(a) | ((uint32_t)__half_as_ushort(b) << 16);
}

// ---------------------------------------------------------------------------
// Kernel 0: weights -> fp16 (hi only)
// ---------------------------------------------------------------------------
__global__ void prep_w(const float* __restrict__ Wat, const float* __restrict__ Wih,
                       const float* __restrict__ Whh) {
    int i = blockIdx.x * 256 + threadIdx.x;
    if (i < FPD * FPD)     g_Wat_h[i] = __float2half_rn(Wat[i]);
    if (i < 3 * FPD * FPD) {
        g_Wih_h[i] = __float2half_rn(Wih[i]);
        g_Whh_h[i] = __float2half_rn(Whh[i]);
    }
}

// ---------------------------------------------------------------------------
// Kernel 1a: per-position projections (unchanged from R12 — passing)
// ---------------------------------------------------------------------------
#define PJ_ATOMS 64
#define PJ_WA  0
#define PJ_WNA (AD * FPD)
#define PJ_WNB (PJ_WNA + AD * FPD)
#define PJ_AR  (PJ_WNB + BD * FPD)
#define PJ_BR  (PJ_AR + 8 * 40)
#define PJ_SMEM ((PJ_BR + 8 * 12) * 4)

__global__ void __launch_bounds__(256, 2) proj_kernel(
    const float* __restrict__ atom_list, const float* __restrict__ bond_list,
    const float* __restrict__ W_atom,    const float* __restrict__ b_atom,
    const float* __restrict__ W_nbr)
{
    extern __shared__ float smem[];
    float* Wa   = smem + PJ_WA;
    float* WnA  = smem + PJ_WNA;
    float* WnB  = smem + PJ_WNB;
    float* arow = smem + PJ_AR;
    float* brow = smem + PJ_BR;

    const int tid = threadIdx.x;
    const int f   = tid;

    for (int i = tid; i < AD * FPD; i += 256) {
        int ff = i / AD, k = i % AD;
        Wa[k * FPD + ff]  = W_atom[ff * AD + k];
        WnA[k * FPD + ff] = W_nbr[ff * CD + k];
    }
    for (int i = tid; i < BD * FPD; i += 256) {
        int ff = i / BD, k = i % BD;
        WnB[k * FPD + ff] = W_nbr[ff * CD + AD + k];
    }
    const float ba = b_atom[f];
    __syncthreads();

    const int base = blockIdx.x * PJ_ATOMS;

    for (int ab = 0; ab < PJ_ATOMS; ab += 8) {
        const int atom0 = base + ab;
        __syncthreads();
        for (int i = tid; i < 8 * 49; i += 256) {
            int a = i / 49, j = i % 49;
            if (j < AD) arow[a * 40 + j] = atom_list[(atom0 + a) * AD + j];
            else        brow[a * 12 + (j - AD)] = bond_list[(atom0 + a) * BD + (j - AD)];
        }
        __syncthreads();

        float af8[8], pa8[8], pb8[8];
        #pragma unroll
        for (int a = 0; a < 8; a++) { af8[a] = ba; pa8[a] = 0.f; pb8[a] = 0.f; }

        #pragma unroll
        for (int k0 = 0; k0 < 36; k0 += 4) {
            float wa0 = Wa[(k0 + 0) * FPD + f], wa1 = Wa[(k0 + 1) * FPD + f];
            float wa2 = Wa[(k0 + 2) * FPD + f], wa3 = Wa[(k0 + 3) * FPD + f];
            float wn0 = WnA[(k0 + 0) * FPD + f], wn1 = WnA[(k0 + 1) * FPD + f];
            float wn2 = WnA[(k0 + 2) * FPD + f], wn3 = WnA[(k0 + 3) * FPD + f];
            #pragma unroll
            for (int a = 0; a < 8; a++) {
                float4 x = *(const float4*)&arow[a * 40 + k0];
                af8[a] += wa0 * x.x + wa1 * x.y + wa2 * x.z + wa3 * x.w;
                pa8[a] += wn0 * x.x + wn1 * x.y + wn2 * x.z + wn3 * x.w;
            }
        }
        {
            float wa0 = Wa[36 * FPD + f], wa1 = Wa[37 * FPD + f], wa2 = Wa[38 * FPD + f];
            float wn0 = WnA[36 * FPD + f], wn1 = WnA[37 * FPD + f], wn2 = WnA[38 * FPD + f];
            #pragma unroll
            for (int a = 0; a < 8; a++) {
                float x0 = arow[a * 40 + 36], x1 = arow[a * 40 + 37], x2 = arow[a * 40 + 38];
                af8[a] += wa0 * x0 + wa1 * x1 + wa2 * x2;
                pa8[a] += wn0 * x0 + wn1 * x1 + wn2 * x2;
            }
        }
        #pragma unroll
        for (int k0 = 0; k0 < 8; k0 += 4) {
            float wb0 = WnB[(k0 + 0) * FPD + f], wb1 = WnB[(k0 + 1) * FPD + f];
            float wb2 = WnB[(k0 + 2) * FPD + f], wb3 = WnB[(k0 + 3) * FPD + f];
            #pragma unroll
            for (int a = 0; a < 8; a++) {
                float4 x = *(const float4*)&brow[a * 12 + k0];
                pb8[a] += wb0 * x.x + wb1 * x.y + wb2 * x.z + wb3 * x.w;
            }
        }
        {
            float wb0 = WnB[8 * FPD + f], wb1 = WnB[9 * FPD + f];
            #pragma unroll
            for (int a = 0; a < 8; a++)
                pb8[a] += wb0 * brow[a * 12 + 8] + wb1 * brow[a * 12 + 9];
        }

        #pragma unroll
        for (int a = 0; a < 8; a++) {
            const int o = (atom0 + a) * FPD + f;
            float afv = leakyf(af8[a]);
            g_af[o] = afv;
            split2h(afv, g_af_hi[o], g_af_lo[o]);
            g_PA[o] = pa8[a];
            g_PB[o] = pb8[a];
        }
    }
}

// ---------------------------------------------------------------------------
// Kernel 1b: attention — WARP-PER-ATOM. Lane owns 8 features.
// Dots via shfl_xor butterfly (all lanes end with sums); no smem, no syncs.
// ---------------------------------------------------------------------------
#define AW_PER_WARP 8   // atoms per warp

__global__ void __launch_bounds__(256) attn2_kernel(
    const int*   __restrict__ adeg,    const int*   __restrict__ bdeg,
    const float* __restrict__ b_nbr,   const float* __restrict__ W_align,
    const float* __restrict__ b_align)
{
    const int tid  = threadIdx.x;
    const int warp = tid >> 5;
    const int lane = tid & 31;
    const int f0   = lane * 8;          // this lane's feature base

    // per-lane constants (8 features each)
    float wal1v[8], wal2v[8], bnv[8];
    {
        float4 a0 = *(const float4*)&W_align[f0];
        float4 a1 = *(const float4*)&W_align[f0 + 4];
        wal1v[0]=a0.x; wal1v[1]=a0.y; wal1v[2]=a0.z; wal1v[3]=a0.w;
        wal1v[4]=a1.x; wal1v[5]=a1.y; wal1v[6]=a1.z; wal1v[7]=a1.w;
        float4 b0 = *(const float4*)&W_align[FPD + f0];
        float4 b1 = *(const float4*)&W_align[FPD + f0 + 4];
        wal2v[0]=b0.x; wal2v[1]=b0.y; wal2v[2]=b0.z; wal2v[3]=b0.w;
        wal2v[4]=b1.x; wal2v[5]=b1.y; wal2v[6]=b1.z; wal2v[7]=b1.w;
        float4 c0 = *(const float4*)&b_nbr[f0];
        float4 c1 = *(const float4*)&b_nbr[f0 + 4];
        bnv[0]=c0.x; bnv[1]=c0.y; bnv[2]=c0.z; bnv[3]=c0.w;
        bnv[4]=c1.x; bnv[5]=c1.y; bnv[6]=c1.z; bnv[7]=c1.w;
    }
    const float bal = b_align[0];

    const int wg_base = (blockIdx.x * 8 + warp) * AW_PER_WARP;

    for (int ai = 0; ai < AW_PER_WARP; ai++) {
        const int atom = wg_base + ai;
        const int bmol = atom / LQ;

        // indices: lanes 0..5 load adeg, 6..11 load bdeg; broadcast by shfl
        int myidx = 0;
        if (lane < MQ)            myidx = adeg[atom * MQ + lane];
        else if (lane < 2 * MQ)   myidx = bdeg[atom * MQ + (lane - MQ)];

        // v[0..6]: align-score partials over this lane's 8 features
        float v[7];
        {
            const float* afp = g_af + atom * FPD + f0;
            float4 x0 = *(const float4*)afp;
            float4 x1 = *(const float4*)(afp + 4);
            v[0] = x0.x*wal1v[0] + x0.y*wal1v[1] + x0.z*wal1v[2] + x0.w*wal1v[3]
                 + x1.x*wal1v[4] + x1.y*wal1v[5] + x1.z*wal1v[6] + x1.w*wal1v[7];
        }

        float nfs[MQ][8];
        float padv[MQ];
        #pragma unroll
        for (int m = 0; m < MQ; m++) {
            int ja = __shfl_sync(0xffffffffu, myidx, m);
            int jb = __shfl_sync(0xffffffffu, myidx, MQ + m);
            padv[m] = (ja == LQ - 1) ? 1.f : 0.f;
            const float* pap = g_PA + (bmol * LQ + ja) * FPD + f0;
            const float* pbp = g_PB + (bmol * LQ + jb) * FPD + f0;
            float4 p0 = *(const float4*)pap;
            float4 p1 = *(const float4*)(pap + 4);
            float4 q0 = *(const float4*)pbp;
            float4 q1 = *(const float4*)(pbp + 4);
            float t[8];
            t[0] = p0.x + q0.x; t[1] = p0.y + q0.y; t[2] = p0.z + q0.z; t[3] = p0.w + q0.w;
            t[4] = p1.x + q1.x; t[5] = p1.y + q1.y; t[6] = p1.z + q1.z; t[7] = p1.w + q1.w;
            float s = 0.f;
            #pragma unroll
            for (int j = 0; j < 8; j++) {
                float u = leakyf(t[j] + bnv[j]);
                nfs[m][j] = u;
                s += u * wal2v[j];
            }
            v[1 + m] = s;
        }

        // butterfly reduce: all lanes end with full sums
        #pragma unroll
        for (int off = 16; off > 0; off >>= 1)
            #pragma unroll
            for (int j = 0; j < 7; j++)
                v[j] += __shfl_xor_sync(0xffffffffu, v[j], off);

        // softmax (per-lane redundant)
        float sc[MQ], mx = -INFINITY;
        #pragma unroll
        for (int m = 0; m < MQ; m++) {
            float s = leakyf(v[0] + v[1 + m] + bal);
            if (padv[m] > 0.5f) s += -9e8f;
            sc[m] = s;
            mx = fmaxf(mx, s);
        }
        float e[MQ], se = 0.f;
        #pragma unroll
        for (int m = 0; m < MQ; m++) { e[m] = expf(sc[m] - mx); se += e[m]; }
        float inv = 1.f / se;
        float aw[MQ], asum = 0.f;
        #pragma unroll
        for (int m = 0; m < MQ; m++) {
            float a = e[m] * inv;
            if (padv[m] > 0.5f) a = 0.f;
            aw[m] = a;
            asum += a;
        }

        // weighted sum + fp16 split store (uint4 per lane per array)
        uint32_t wh[4], wl[4];
        #pragma unroll
        for (int q = 0; q < 4; q++) {
            float s0 = 0.f, s1 = 0.f;
            #pragma unroll
            for (int m = 0; m < MQ; m++) {
                s0 += aw[m] * nfs[m][2 * q];
                s1 += aw[m] * nfs[m][2 * q + 1];
            }
            __half h0, l0, h1, l1;
            split2h(s0, h0, l0); split2h(s1, h1, l1);
            wh[q] = pk2h(h0, h1);
            wl[q] = pk2h(l0, l1);
        }
        const int o = atom * FPD + f0;
        *(uint4*)&g_s_hi[o] = make_uint4(wh[0], wh[1], wh[2], wh[3]);
        *(uint4*)&g_s_lo[o] = make_uint4(wl[0], wl[1], wl[2], wl[3]);
        if (lane == 0) g_asum[atom] = asum;
    }
}

// ---------------------------------------------------------------------------
// Kernel 2a: ctx — fp16 2-pass (unchanged from R12)
// ---------------------------------------------------------------------------
#define CTX_AH 0
#define CTX_AL 10240
#define CTX_BH 20480
#define CTX_BUF 25600
#define CTX_BATT (2 * CTX_BUF)
#define CTX_SMEM (CTX_BATT + 256)

__global__ void __launch_bounds__(256) ctx_mma(const float* __restrict__ batt_g)
{
    extern __shared__ char sm[];
    const uint32_t sb = s2u(sm);
    float* sbatt = (float*)(sm + CTX_BATT);
    const int tid = threadIdx.x, wid = tid >> 5, lane = tid & 31;
    const int m0 = blockIdx.x * 128, n0 = blockIdx.y * 64;
    const int Moff = (wid & 3) * 32, Noff = (wid >> 2) * 32;

    if (tid < 64) sbatt[tid] = batt_g[n0 + tid];

    const int r_ = tid >> 2, q_ = tid & 3;
    const uint32_t soff = (uint32_t)(r_ * 80 + q_ * 16);
    const int aoff0 = (m0 + r_) * FPD + q_ * 8;
    const int aoff1 = (m0 + 64 + r_) * FPD + q_ * 8;
    const int boff  = (n0 + r_) * FPD + q_ * 8;

    const uint32_t a_lo = (uint32_t)((lane & 15) * 80 + (lane >> 4) * 16);
    const uint32_t b_lo = (uint32_t)(((lane & 7) + ((lane >> 4) << 3)) * 80 + ((lane >> 3) & 1) * 16);

    const int row0 = lane >> 2, qb = lane & 3;
    float acc[2][4][4] = {};

    cpa16(sb + CTX_AH + soff,        g_s_hi + aoff0);
    cpa16(sb + CTX_AH + 5120 + soff, g_s_hi + aoff1);
    cpa16(sb + CTX_AL + soff,        g_s_lo + aoff0);
    cpa16(sb + CTX_AL + 5120 + soff, g_s_lo + aoff1);
    cpa16(sb + CTX_BH + soff, g_Wat_h + boff);
    CP_COMMIT();

    for (int c = 0; c < 8; c++) {
        CP_WAIT0();
        __syncthreads();
        if (c < 7) {
            const int k0 = (c + 1) * 32;
            const uint32_t bo = ((c + 1) & 1) * CTX_BUF;
            cpa16(sb + bo + CTX_AH + soff,        g_s_hi + aoff0 + k0);
            cpa16(sb + bo + CTX_AH + 5120 + soff, g_s_hi + aoff1 + k0);
            cpa16(sb + bo + CTX_AL + soff,        g_s_lo + aoff0 + k0);
            cpa16(sb + bo + CTX_AL + 5120 + soff, g_s_lo + aoff1 + k0);
            cpa16(sb + bo + CTX_BH + soff, g_Wat_h + boff + k0);
            CP_COMMIT();
        }
        const uint32_t bb = sb + (c & 1) * CTX_BUF;
        #pragma unroll
        for (int ks = 0; ks < 2; ks++) {
            uint32_t ah[2][4], al[2][4];
            #pragma unroll
            for (int mt = 0; mt < 2; mt++) {
                uint32_t ao = (uint32_t)((Moff + mt * 16) * 80) + a_lo + ks * 32;
                ldm4(ah[mt], bb + CTX_AH + ao);
                ldm4(al[mt], bb + CTX_AL + ao);
            }
            uint32_t bh[2][4];
            #pragma unroll
            for (int p = 0; p < 2; p++) {
                uint32_t bo2 = (uint32_t)((Noff + p * 16) * 80) + b_lo + ks * 32;
                ldm4(bh[p], bb + CTX_BH + bo2);
            }
            #pragma unroll
            for (int mt = 0; mt < 2; mt++)
                #pragma unroll
                for (int nt = 0; nt < 4; nt++) {
                    const uint32_t* Bh = &bh[nt >> 1][(nt & 1) * 2];
                    mma16816(acc[mt][nt], ah[mt], Bh);
                    mma16816(acc[mt][nt], al[mt], Bh);
                }
        }
    }

    #pragma unroll
    for (int mt = 0; mt < 2; mt++) {
        int r0 = m0 + Moff + mt * 16 + row0;
        float as0 = g_asum[r0], as1 = g_asum[r0 + 8];
        #pragma unroll
        for (int nt = 0; nt < 4; nt++) {
            int cl = Noff + nt * 8 + qb * 2;
            int col = n0 + cl;
            float b0 = sbatt[cl], b1 = sbatt[cl + 1];
            float t00 = acc[mt][nt][0] + as0 * b0, t01 = acc[mt][nt][1] + as0 * b1;
            float t10 = acc[mt][nt][2] + as1 * b0, t11 = acc[mt][nt][3] + as1 * b1;
            t00 = t00 > 0.f ? t00 : expm1f(t00);
            t01 = t01 > 0.f ? t01 : expm1f(t01);
            t10 = t10 > 0.f ? t10 : expm1f(t10);
            t11 = t11 > 0.f ? t11 : expm1f(t11);
            __half h0, l0, h1, l1;
            split2h(t00, h0, l0); split2h(t01, h1, l1);
            *(uint32_t*)&g_cx_hi[r0 * FPD + col] = pk2h(h0, h1);
            *(uint32_t*)&g_cx_lo[r0 * FPD + col] = pk2h(l0, l1);
            split2h(t10, h0, l0); split2h(t11, h1, l1);
            *(uint32_t*)&g_cx_hi[(r0 + 8) * FPD + col] = pk2h(h0, h1);
            *(uint32_t*)&g_cx_lo[(r0 + 8) * FPD + col] = pk2h(l0, l1);
        }
    }
}

// ---------------------------------------------------------------------------
// Kernel 2b: GRU — fp16 2-pass, 3 CTAs/SM (unchanged from R12)
// ---------------------------------------------------------------------------
#define GTA     5120
#define GTB     2560
#define GB_B    (4 * GTA)
#define GB_BUF  (GB_B + 6 * GTB)
#define GB_BIAS (2 * GB_BUF)
#define GB_SMEM (GB_BIAS + 768 + 32)

__global__ void __launch_bounds__(256, 3) gru_mma(
    const float* __restrict__ b_ih, const float* __restrict__ b_hh,
    float* __restrict__ out)
{
    extern __shared__ char sm[];
    const uint32_t sb = s2u(sm);
    float* sbias = (float*)(sm + GB_BIAS);
    const int tid = threadIdx.x, wid = tid >> 5, lane = tid & 31;
    const int m0 = blockIdx.x * 64, f0 = blockIdx.y * 32;
    const int Moff = (wid >> 1) * 16, Noff = (wid & 1) * 16;

    if (tid < 192) {
        int g = tid >> 5, fl = tid & 31;
        sbias[tid] = (g < 3) ? b_ih[g * FPD + f0 + fl] : b_hh[(g - 3) * FPD + f0 + fl];
    }

    const int rA = tid >> 2;
    const int half = tid >> 7;
    const int rB = (tid >> 2) & 31;
    const int sg = tid & 3;
    const uint32_t aoffS = (uint32_t)(rA * 80 + sg * 16);
    const uint32_t boffS = (uint32_t)(rB * 80 + sg * 16);
    const int aRow  = (m0 + rA) * FPD + sg * 8;
    const int bRow0 = (0 * FPD + f0 + rB) * FPD + sg * 8;
    const int bRow1 = (1 * FPD + f0 + rB) * FPD + sg * 8;
    const int bRow2 = (2 * FPD + f0 + rB) * FPD + sg * 8;

    const __half* srcA[4] = { g_cx_hi, g_cx_lo, g_af_hi, g_af_lo };
    const __half* wsrc = half ? g_Whh_h : g_Wih_h;
    const int bRow[3] = { bRow0, bRow1, bRow2 };
    const int gBase = half * 3;

    const uint32_t a_lo = (uint32_t)((lane & 15) * 80 + (lane >> 4) * 16);
    const uint32_t b_lo = (uint32_t)(((lane & 7) + ((lane >> 4) << 3)) * 80 + ((lane >> 3) & 1) * 16);

    const int row0 = lane >> 2, qb = lane & 3;
    float acc[6][2][4] = {};

    #pragma unroll
    for (int t = 0; t < 4; t++) cpa16(sb + (uint32_t)(t * GTA) + aoffS, srcA[t] + aRow);
    #pragma unroll
    for (int j = 0; j < 3; j++)
        cpa16(sb + GB_B + (uint32_t)((gBase + j) * GTB) + boffS, wsrc + bRow[j]);
    CP_COMMIT();

    for (int c = 0; c < 8; c++) {
        CP_WAIT0();
        __syncthreads();
        if (c < 7) {
            const int k0 = (c + 1) * 32;
            const uint32_t bs = sb + ((c + 1) & 1) * GB_BUF;
            #pragma unroll
            for (int t = 0; t < 4; t++)
                cpa16(bs + (uint32_t)(t * GTA) + aoffS, srcA[t] + aRow + k0);
            #pragma unroll
            for (int j = 0; j < 3; j++)
                cpa16(bs + GB_B + (uint32_t)((gBase + j) * GTB) + boffS, wsrc + bRow[j] + k0);
            CP_COMMIT();
        }
        const uint32_t bb = sb + (c & 1) * GB_BUF;
        #pragma unroll
        for (int ks = 0; ks < 2; ks++) {
            uint32_t Ah[2][4], Al[2][4];
            #pragma unroll
            for (int am = 0; am < 2; am++) {
                uint32_t ao = (uint32_t)(Moff * 80) + a_lo + ks * 32;
                ldm4(Ah[am], bb + (uint32_t)((am * 2) * GTA) + ao);
                ldm4(Al[am], bb + (uint32_t)((am * 2 + 1) * GTA) + ao);
            }
            #pragma unroll
            for (int g = 0; g < 6; g++) {
                uint32_t bhf[4];
                uint32_t bo2 = (uint32_t)(Noff * 80) + b_lo + ks * 32;
                ldm4(bhf, bb + GB_B + (uint32_t)(g * GTB) + bo2);
                const int am = (g < 3) ? 0 : 1;
                #pragma unroll
                for (int nt = 0; nt < 2; nt++) {
                    const uint32_t* Bh = &bhf[nt * 2];
                    mma16816(acc[g][nt], Ah[am], Bh);
                    mma16816(acc[g][nt], Al[am], Bh);
                }
            }
        }
    }

    #pragma unroll
    for (int rp = 0; rp < 2; rp++) {
        int row = m0 + Moff + row0 + rp * 8;
        #pragma unroll
        for (int nt = 0; nt < 2; nt++) {
            int cl = Noff + nt * 8 + qb * 2;
            int colG = f0 + cl;
            float o2[2];
            #pragma unroll
            for (int j = 0; j < 2; j++) {
                int ci = rp * 2 + j;
                float ir  = acc[0][nt][ci] + sbias[cl + j];
                float iz  = acc[1][nt][ci] + sbias[32 + cl + j];
                float in_ = acc[2][nt][ci] + sbias[64 + cl + j];
                float hr  = acc[3][nt][ci] + sbias[96 + cl + j];
                float hz  = acc[4][nt][ci] + sbias[128 + cl + j];
                float hn  = acc[5][nt][ci] + sbias[160 + cl + j];
                float r = sigmf(ir + hr), z = sigmf(iz + hz);
                float n = tanhf(in_ + r * hn);
                float h = g_af[row * FPD + colG + j];
                o2[j] = fmaxf((1.f - z) * n + z * h, 0.f);
            }
            *(float2*)&out[row * FPD + colG] = make_float2(o2[0], o2[1]);
        }
    }
}

// ---------------------------------------------------------------------------
// Launcher
// ---------------------------------------------------------------------------
extern "C" void kernel_launch(void* const* d_in, const int* in_sizes, int n_in,
                              void* d_out, int out_size)
{
    const float* atom_list = (const float*)d_in[0];
    const float* bond_list = (const float*)d_in[1];
    const int*   adeg      = (const int*)  d_in[2];
    const int*   bdeg      = (const int*)  d_in[3];
    const float* W_atom   = (const float*)d_in[5];
    const float* b_atom   = (const float*)d_in[6];
    const float* W_nbr    = (const float*)d_in[7];
    const float* b_nbr    = (const float*)d_in[8];
    const float* W_align  = (const float*)d_in[9];
    const float* b_align  = (const float*)d_in[10];
    const float* W_attend = (const float*)d_in[11];
    const float* b_attend = (const float*)d_in[12];
    const float* W_ih     = (const float*)d_in[13];
    const float* b_ih     = (const float*)d_in[14];
    const float* W_hh     = (const float*)d_in[15];
    const float* b_hh     = (const float*)d_in[16];
    float* out = (float*)d_out;
    (void)in_sizes; (void)n_in; (void)out_size;

    cudaFuncSetAttribute(proj_kernel, cudaFuncAttributeMaxDynamicSharedMemorySize, PJ_SMEM);
    cudaFuncSetAttribute(ctx_mma,     cudaFuncAttributeMaxDynamicSharedMemorySize, CTX_SMEM);
    cudaFuncSetAttribute(gru_mma,     cudaFuncAttributeMaxDynamicSharedMemorySize, GB_SMEM);

    prep_w<<<(3 * FPD * FPD + 255) / 256, 256>>>(W_attend, W_ih, W_hh);

    proj_kernel<<<NATOMS / PJ_ATOMS, 256, PJ_SMEM>>>(
        atom_list, bond_list, W_atom, b_atom, W_nbr);

    attn2_kernel<<<NATOMS / 64, 256>>>(adeg, bdeg, b_nbr, W_align, b_align);

    dim3 gc(NATOMS / 128, FPD / 64);
    ctx_mma<<<gc, 256, CTX_SMEM>>>(b_attend);

    dim3 gg(NATOMS / 64, FPD / 32);
    gru_mma<<<gg, 256, GB_SMEM>>>(b_ih, b_hh, out);
}